// round 4
// baseline (speedup 1.0000x reference)
#include <cuda_runtime.h>
#include <math.h>

#define CB 4
#define CN 1024
#define CM 1024
#define CH 512

// ---------------- scratch (device globals; no allocation allowed) ----------------
__device__ __align__(16) float g_e  [CB*CN*CH];
__device__ __align__(16) float g_e1 [CB*CN*CH];
__device__ __align__(16) float g_e2 [CB*CN*CH];
__device__ __align__(16) float g_e3 [CB*CN*CH];
__device__ __align__(16) float g_K  [CB*CN*CH];
__device__ __align__(16) float g_V  [CB*CN*CH];
__device__ __align__(16) float g_Q  [CB*CN*CH];
__device__ __align__(16) float g_K2 [CB*CN*CH];
__device__ __align__(16) float g_V2 [CB*CN*CH];
__device__ __align__(16) float g_Q2 [CB*CN*CH];
__device__ __align__(16) float g_r  [CB*CN*CH];
__device__ __align__(16) float g_t  [CB*CN*CH];
__device__ __align__(16) float g_q  [CB*CM*CH];
__device__ __align__(16) float g_k0 [CB*CN*CH];
__device__ __align__(16) float g_S  [16u*1024u*1024u];   // max Z=16 score matrices

// ---------------- batched GEMM: C = alpha*(A @ B(^T)) [+ bias] [+ C] ----------------
// A: (M,K) lda ; B: (K,N) ldb  or TRB: (N,K) ldb ; C: (M,N) ldc
// z -> (bb = z/nH, hh = z%nH); each operand offset by bb*stride_batch + hh*stride_head
#define BM 128
#define BN 128
#define BK 16

template<bool ACC, bool TRB>
__global__ __launch_bounds__(256) void gemm_k(
    const float* __restrict__ A, int lda, long aB, long aH,
    const float* __restrict__ Bm, int ldb, long bB, long bH,
    float* __restrict__ C, int ldc, long cB, long cH,
    int K, int nH, float alpha, const float* __restrict__ bias)
{
    int z = blockIdx.z;
    int bb = z / nH, hh = z - bb * nH;
    A  += (size_t)bb * aB + (size_t)hh * aH;
    Bm += (size_t)bb * bB + (size_t)hh * bH;
    C  += (size_t)bb * cB + (size_t)hh * cH;

    __shared__ __align__(16) float As[BK][BM + 4];
    __shared__ __align__(16) float Bs[BK][BN + 4];

    int tid = threadIdx.x;
    int tx = tid & 15, ty = tid >> 4;
    int rowBase = blockIdx.y * BM;
    int colBase = blockIdx.x * BN;

    float acc[8][8];
#pragma unroll
    for (int i = 0; i < 8; i++)
#pragma unroll
        for (int j = 0; j < 8; j++) acc[i][j] = 0.f;

    for (int k0 = 0; k0 < K; k0 += BK) {
#pragma unroll
        for (int t = 0; t < 8; t++) {
            int i = tid + t * 256;
            int r = i >> 4, kk = i & 15;
            As[kk][r] = A[(size_t)(rowBase + r) * lda + (k0 + kk)];
        }
#pragma unroll
        for (int t = 0; t < 8; t++) {
            int i = tid + t * 256;
            if (TRB) {
                int n = i >> 4, kk = i & 15;
                Bs[kk][n] = Bm[(size_t)(colBase + n) * ldb + (k0 + kk)];
            } else {
                int kk = i >> 7, n = i & 127;
                Bs[kk][n] = Bm[(size_t)(k0 + kk) * ldb + (colBase + n)];
            }
        }
        __syncthreads();
#pragma unroll
        for (int kk = 0; kk < BK; kk++) {
            float4 a0 = *(const float4*)&As[kk][ty * 8];
            float4 a1 = *(const float4*)&As[kk][ty * 8 + 4];
            float4 b0 = *(const float4*)&Bs[kk][tx * 8];
            float4 b1 = *(const float4*)&Bs[kk][tx * 8 + 4];
            float a[8] = {a0.x, a0.y, a0.z, a0.w, a1.x, a1.y, a1.z, a1.w};
            float b[8] = {b0.x, b0.y, b0.z, b0.w, b1.x, b1.y, b1.z, b1.w};
#pragma unroll
            for (int i = 0; i < 8; i++)
#pragma unroll
                for (int j = 0; j < 8; j++)
                    acc[i][j] += a[i] * b[j];
        }
        __syncthreads();
    }

#pragma unroll
    for (int i = 0; i < 8; i++) {
        size_t roff = (size_t)(rowBase + ty * 8 + i) * ldc + colBase + tx * 8;
#pragma unroll
        for (int v = 0; v < 2; v++) {
            float4 val;
            val.x = acc[i][v * 4 + 0] * alpha;
            val.y = acc[i][v * 4 + 1] * alpha;
            val.z = acc[i][v * 4 + 2] * alpha;
            val.w = acc[i][v * 4 + 3] * alpha;
            if (bias) {
                float4 bv = *(const float4*)&bias[colBase + tx * 8 + v * 4];
                val.x += bv.x; val.y += bv.y; val.z += bv.z; val.w += bv.w;
            }
            if (ACC) {
                float4 old = *(float4*)&C[roff + v * 4];
                val.x += old.x; val.y += old.y; val.z += old.z; val.w += old.w;
            }
            *(float4*)&C[roff + v * 4] = val;
        }
    }
}

template<bool ACC, bool TRB>
static void G(const float* A, int lda, long aB, long aH,
              const float* Bm, int ldb, long bB, long bH,
              float* C, int ldc, long cB, long cH,
              int M, int N, int K, int Z, int nH, float alpha, const float* bias)
{
    dim3 grid(N / BN, M / BM, Z);
    gemm_k<ACC, TRB><<<grid, 256>>>(A, lda, aB, aH, Bm, ldb, bB, bH,
                                    C, ldc, cB, cH, K, nH, alpha, bias);
}

// ---------------- row softmax (row length n = 1024) ----------------
__global__ void softmax_k(float* __restrict__ S, int n)
{
    float* row = S + (size_t)blockIdx.x * n;
    __shared__ float red[256];
    int tid = threadIdx.x;
    float m = -3.4e38f;
    for (int i = tid; i < n; i += 256) m = fmaxf(m, row[i]);
    red[tid] = m; __syncthreads();
    for (int st = 128; st; st >>= 1) { if (tid < st) red[tid] = fmaxf(red[tid], red[tid + st]); __syncthreads(); }
    m = red[0]; __syncthreads();
    float s = 0.f;
    for (int i = tid; i < n; i += 256) { float ev = __expf(row[i] - m); row[i] = ev; s += ev; }
    red[tid] = s; __syncthreads();
    for (int st = 128; st; st >>= 1) { if (tid < st) red[tid] += red[tid + st]; __syncthreads(); }
    float inv = 1.f / red[0];
    for (int i = tid; i < n; i += 256) row[i] *= inv;
}

// ---------------- out = LayerNorm(t + res) * g + b  (row length CH) ----------------
__global__ void add_ln_k(const float* __restrict__ t, const float* __restrict__ res,
                         const float* __restrict__ g, const float* __restrict__ b,
                         float* __restrict__ out)
{
    __shared__ float buf[CH];
    __shared__ float red[256];
    size_t off = (size_t)blockIdx.x * CH;
    int tid = threadIdx.x;
    float s = 0.f;
    for (int i = tid; i < CH; i += 256) { float y = t[off + i] + res[off + i]; buf[i] = y; s += y; }
    red[tid] = s; __syncthreads();
    for (int st = 128; st; st >>= 1) { if (tid < st) red[tid] += red[tid + st]; __syncthreads(); }
    float mean = red[0] * (1.f / CH);
    __syncthreads();
    float v = 0.f;
    for (int i = tid; i < CH; i += 256) { float d = buf[i] - mean; v += d * d; }
    red[tid] = v; __syncthreads();
    for (int st = 128; st; st >>= 1) { if (tid < st) red[tid] += red[tid + st]; __syncthreads(); }
    float rstd = rsqrtf(red[0] * (1.f / CH) + 1e-5f);
    for (int i = tid; i < CH; i += 256) out[off + i] = (buf[i] - mean) * rstd * g[i] + b[i];
}

// ---------------- input projections ----------------
// e[bn, j] = cx[bn]*W[0,j] + y0*W[1,j] + y1*W[2,j] + b[j],  y = cy[bn, dom*2 .. dom*2+1]
__global__ void proj_in_k(const float* __restrict__ cx, const float* __restrict__ cy,
                          const float* __restrict__ W, const float* __restrict__ b,
                          float* __restrict__ out, int dom)
{
    int idx = blockIdx.x * blockDim.x + threadIdx.x;
    int j = idx & (CH - 1);
    int bn = idx >> 9;
    float x0 = cx[bn];
    const float* y = cy + (size_t)bn * 8 + dom * 2;
    out[idx] = fmaf(x0, W[j], fmaf(y[0], W[CH + j], fmaf(y[1], W[2 * CH + j], b[j])));
}

// out[i, j] = x[i]*W[j] + b[j]   (K=1 projection)
__global__ void proj1_k(const float* __restrict__ x, const float* __restrict__ W,
                        const float* __restrict__ b, float* __restrict__ out)
{
    int idx = blockIdx.x * blockDim.x + threadIdx.x;
    int j = idx & (CH - 1);
    int i = idx >> 9;
    out[idx] = fmaf(x[i], W[j], b[j]);
}

// ---------------- orchestration ----------------
extern "C" void kernel_launch(void* const* d_in, const int* in_sizes, int n_in,
                              void* d_out, int out_size)
{
    const float* cx    = (const float*)d_in[0];
    const float* cy    = (const float*)d_in[1];
    const float* txp   = (const float*)d_in[2];
    const float* in_W  = (const float*)d_in[3];
    const float* in_b  = (const float*)d_in[4];
    const float* cx_W  = (const float*)d_in[5];
    const float* cx_b  = (const float*)d_in[6];
    const float* tx_W  = (const float*)d_in[7];
    const float* tx_b  = (const float*)d_in[8];
    const float* sc_Wk = (const float*)d_in[9];
    const float* sc_Wv = (const float*)d_in[10];
    const float* sc_Wq = (const float*)d_in[11];
    const float* sc_Wf = (const float*)d_in[12];
    const float* sc_bf = (const float*)d_in[13];
    const float* sc_g  = (const float*)d_in[14];
    const float* sc_b  = (const float*)d_in[15];
    const float* ca_Wk = (const float*)d_in[16];
    const float* ca_Wv = (const float*)d_in[17];
    const float* ca_Wq = (const float*)d_in[18];
    const float* ca_Wf = (const float*)d_in[19];
    const float* ca_bf = (const float*)d_in[20];
    const float* ca_g  = (const float*)d_in[21];
    const float* ca_b  = (const float*)d_in[22];

    void* p;
    cudaGetSymbolAddress(&p, g_e);  float* e   = (float*)p;
    cudaGetSymbolAddress(&p, g_e1); float* e1b = (float*)p;
    cudaGetSymbolAddress(&p, g_e2); float* e2b = (float*)p;
    cudaGetSymbolAddress(&p, g_e3); float* e3b = (float*)p;
    cudaGetSymbolAddress(&p, g_K);  float* Kb  = (float*)p;
    cudaGetSymbolAddress(&p, g_V);  float* Vb  = (float*)p;
    cudaGetSymbolAddress(&p, g_Q);  float* Qb  = (float*)p;
    cudaGetSymbolAddress(&p, g_K2); float* K2b = (float*)p;
    cudaGetSymbolAddress(&p, g_V2); float* V2b = (float*)p;
    cudaGetSymbolAddress(&p, g_Q2); float* Q2b = (float*)p;
    cudaGetSymbolAddress(&p, g_r);  float* rb  = (float*)p;
    cudaGetSymbolAddress(&p, g_t);  float* tb  = (float*)p;
    cudaGetSymbolAddress(&p, g_q);  float* qb  = (float*)p;
    cudaGetSymbolAddress(&p, g_k0); float* k0b = (float*)p;
    cudaGetSymbolAddress(&p, g_S);  float* Sb  = (float*)p;

    const int totE = CB * CN * CH;

    // input projections: e = proj(y[:,:,0,:]) etc., q/k seeds
    proj_in_k<<<totE / 256, 256>>>(cx, cy, in_W, in_b, e,   0);
    proj_in_k<<<totE / 256, 256>>>(cx, cy, in_W, in_b, e1b, 1);
    proj_in_k<<<totE / 256, 256>>>(cx, cy, in_W, in_b, e2b, 2);
    proj_in_k<<<totE / 256, 256>>>(cx, cy, in_W, in_b, e3b, 3);
    proj1_k<<<(CB * CM * CH) / 256, 256>>>(txp, tx_W, tx_b, qb);
    proj1_k<<<totE / 256, 256>>>(cx, cx_W, cx_b, k0b);

    // one _sc_attn layer: x = e (in place), x2 given; self==true -> x2 == x (4 identical sdpa = 4*sdpa)
    auto sc_layer = [&](const float* x2, bool self, int i) {
        const float* Wk = sc_Wk + (size_t)i * CH * CH;
        const float* Wv = sc_Wv + (size_t)i * CH * CH;
        const float* Wq = sc_Wq + (size_t)i * CH * CH;
        const float* Wf = sc_Wf + (size_t)i * 2 * CH * CH;
        const float* bf = sc_bf + (size_t)i * CH;
        const float* lg = sc_g  + (size_t)i * CH;
        const float* lb = sc_b  + (size_t)i * CH;
        const int R = CB * CN;
        G<false, false>(e, CH, 0, 0, Wk, CH, 0, 0, Kb, CH, 0, 0, R, CH, CH, 1, 1, 1.f, nullptr);
        G<false, false>(e, CH, 0, 0, Wv, CH, 0, 0, Vb, CH, 0, 0, R, CH, CH, 1, 1, 1.f, nullptr);
        G<false, false>(e, CH, 0, 0, Wq, CH, 0, 0, Qb, CH, 0, 0, R, CH, CH, 1, 1, 1.f, nullptr);
        if (!self) {
            G<false, false>(x2, CH, 0, 0, Wk, CH, 0, 0, K2b, CH, 0, 0, R, CH, CH, 1, 1, 1.f, nullptr);
            G<false, false>(x2, CH, 0, 0, Wv, CH, 0, 0, V2b, CH, 0, 0, R, CH, CH, 1, 1, 1.f, nullptr);
            G<false, false>(x2, CH, 0, 0, Wq, CH, 0, 0, Q2b, CH, 0, 0, R, CH, CH, 1, 1, 1.f, nullptr);
        }
        const int d = 256, h = 2, Z = CB * h;
        const float* Qs[4] = {Qb, Q2b, Q2b, Qb};
        const float* Ks[4] = {Kb, K2b, Kb, K2b};
        const float* Vs[4] = {Vb, V2b, Vb, V2b};
        int nT = self ? 1 : 4;
        for (int t = 0; t < nT; t++) {
            G<false, true>(Qs[t], CH, (long)CN * CH, d, Ks[t], CH, (long)CN * CH, d,
                           Sb, CN, (long)h * CN * CN, (long)CN * CN,
                           CN, CN, d, Z, h, 0.0625f, nullptr);  // 1/sqrt(256)
            softmax_k<<<Z * CN, 256>>>(Sb, CN);
            float ao = self ? 4.f : 1.f;
            if (t == 0)
                G<false, false>(Sb, CN, (long)h * CN * CN, (long)CN * CN, Vs[t], CH, (long)CN * CH, d,
                                rb, CH, (long)CN * CH, d, CN, d, CN, Z, h, ao, nullptr);
            else
                G<true, false>(Sb, CN, (long)h * CN * CN, (long)CN * CN, Vs[t], CH, (long)CN * CH, d,
                               rb, CH, (long)CN * CH, d, CN, d, CN, Z, h, 1.f, nullptr);
        }
        // t = concat(e, r) @ Wf + bf = e@Wf_top + r@Wf_bot + bf
        G<false, false>(e,  CH, 0, 0, Wf,            CH, 0, 0, tb, CH, 0, 0, R, CH, CH, 1, 1, 1.f, bf);
        G<true,  false>(rb, CH, 0, 0, Wf + CH * CH,  CH, 0, 0, tb, CH, 0, 0, R, CH, CH, 1, 1, 1.f, nullptr);
        add_ln_k<<<R, 256>>>(tb, e, lg, lb, e);
    };

    sc_layer(e,   true,  0); sc_layer(e,   true,  1);
    sc_layer(e1b, false, 0); sc_layer(e1b, false, 1);
    sc_layer(e2b, false, 0); sc_layer(e2b, false, 1);
    sc_layer(e3b, false, 0); sc_layer(e3b, false, 1);

    // cross attention: q = _attn(k0, e, q) twice, h=4, d=128
    for (int i = 0; i < 2; i++) {
        const float* Wk = ca_Wk + (size_t)i * CH * CH;
        const float* Wv = ca_Wv + (size_t)i * CH * CH;
        const float* Wq = ca_Wq + (size_t)i * CH * CH;
        const float* Wf = ca_Wf + (size_t)i * 2 * CH * CH;
        const float* bf = ca_bf + (size_t)i * CH;
        const float* lg = ca_g  + (size_t)i * CH;
        const float* lb = ca_b  + (size_t)i * CH;
        const int R = CB * CM;
        G<false, false>(k0b, CH, 0, 0, Wk, CH, 0, 0, Kb, CH, 0, 0, CB * CN, CH, CH, 1, 1, 1.f, nullptr);
        G<false, false>(e,   CH, 0, 0, Wv, CH, 0, 0, Vb, CH, 0, 0, CB * CN, CH, CH, 1, 1, 1.f, nullptr);
        G<false, false>(qb,  CH, 0, 0, Wq, CH, 0, 0, Qb, CH, 0, 0, R,       CH, CH, 1, 1, 1.f, nullptr);
        const int d = 128, h = 4, Z = CB * h;
        G<false, true>(Qb, CH, (long)CM * CH, d, Kb, CH, (long)CN * CH, d,
                       Sb, CN, (long)h * CM * CN, (long)CM * CN,
                       CM, CN, d, Z, h, 0.0883883476483184f, nullptr);  // 1/sqrt(128)
        softmax_k<<<Z * CM, 256>>>(Sb, CN);
        G<false, false>(Sb, CN, (long)h * CM * CN, (long)CM * CN, Vb, CH, (long)CN * CH, d,
                        rb, CH, (long)CM * CH, d, CM, d, CN, Z, h, 1.f, nullptr);
        G<false, false>(qb, CH, 0, 0, Wf,           CH, 0, 0, tb, CH, 0, 0, R, CH, CH, 1, 1, 1.f, bf);
        G<true,  false>(rb, CH, 0, 0, Wf + CH * CH, CH, 0, 0, tb, CH, 0, 0, R, CH, CH, 1, 1, 1.f, nullptr);
        add_ln_k<<<R, 256>>>(tb, qb, lg, lb, (i == 1) ? (float*)d_out : qb);
    }
}

// round 5
// speedup vs baseline: 1.3497x; 1.3497x over previous
#include <cuda_runtime.h>
#include <math.h>

#define CB 4
#define CN 1024
#define CM 1024
#define CH 512

// ---------------- scratch (device globals; no allocation allowed) ----------------
__device__ __align__(16) float g_e  [CB*CN*CH];
__device__ __align__(16) float g_e1 [CB*CN*CH];
__device__ __align__(16) float g_e2 [CB*CN*CH];
__device__ __align__(16) float g_e3 [CB*CN*CH];
__device__ __align__(16) float g_K  [CB*CN*CH];
__device__ __align__(16) float g_V  [CB*CN*CH];
__device__ __align__(16) float g_Q  [CB*CN*CH];
__device__ __align__(16) float g_K2 [CB*CN*CH];
__device__ __align__(16) float g_V2 [CB*CN*CH];
__device__ __align__(16) float g_Q2 [CB*CN*CH];
__device__ __align__(16) float g_r  [CB*CN*CH];
__device__ __align__(16) float g_t  [CB*CN*CH];
__device__ __align__(16) float g_q  [CB*CM*CH];
__device__ __align__(16) float g_k0 [CB*CN*CH];
__device__ __align__(16) float g_S  [16u*1024u*1024u];   // max Z=16 score matrices

// ---------------- batched GEMM: C = alpha*(A @ B(^T)) [+ bias] [+ C] ----------------
// A: (M,K) lda ; B: (K,N) ldb  or TRB: (N,K) ldb ; C: (M,N) ldc
// Double-buffered 128x128x8 tiles, float4 global loads, 1 barrier/tile.
#define BM 128
#define BN 128
#define BK 8
#define SPAD 132   // padded smem row stride (floats)

template<bool ACC, bool TRB>
__global__ __launch_bounds__(256, 2) void gemm_k(
    const float* __restrict__ A, int lda, long aB, long aH,
    const float* __restrict__ Bm, int ldb, long bB, long bH,
    float* __restrict__ C, int ldc, long cB, long cH,
    int K, int nH, float alpha, const float* __restrict__ bias)
{
    int z = blockIdx.z;
    int bb = z / nH, hh = z - bb * nH;
    A  += (size_t)bb * aB + (size_t)hh * aH;
    Bm += (size_t)bb * bB + (size_t)hh * bH;
    C  += (size_t)bb * cB + (size_t)hh * cH;

    __shared__ __align__(16) float As[2][BK][SPAD];
    __shared__ __align__(16) float Bs[2][BK][SPAD];

    int tid = threadIdx.x;
    int tx = tid & 15, ty = tid >> 4;
    int rowBase = blockIdx.y * BM;
    int colBase = blockIdx.x * BN;

    // --- global load addressing ---
    // A: thread loads float4 along k. row = tid>>1, kq = (tid&1)*4
    int arow = tid >> 1;
    int aq   = (tid & 1) * 4;
    const float* Ag = A + (size_t)(rowBase + arow) * lda + aq;

    // B (TRB): same pattern over N rows. B (!TRB): float4 along n, row k = tid>>5.
    int bn   = tid >> 1;          // TRB
    int bq   = (tid & 1) * 4;     // TRB
    int brow = tid >> 5;          // !TRB (0..7)
    int bcol = (tid & 31) * 4;    // !TRB
    const float* Bg = TRB ? (Bm + (size_t)(colBase + bn) * ldb + bq)
                          : (Bm + (size_t)brow * ldb + colBase + bcol);

    float acc[8][8];
#pragma unroll
    for (int i = 0; i < 8; i++)
#pragma unroll
        for (int j = 0; j < 8; j++) acc[i][j] = 0.f;

    int nT = K / BK;

    // --- prologue: tile 0 -> buffer 0 ---
    {
        float4 pa = *(const float4*)Ag;
        float4 pb = TRB ? *(const float4*)Bg
                        : *(const float4*)Bg;
        As[0][aq + 0][arow] = pa.x;
        As[0][aq + 1][arow] = pa.y;
        As[0][aq + 2][arow] = pa.z;
        As[0][aq + 3][arow] = pa.w;
        if (TRB) {
            Bs[0][bq + 0][bn] = pb.x;
            Bs[0][bq + 1][bn] = pb.y;
            Bs[0][bq + 2][bn] = pb.z;
            Bs[0][bq + 3][bn] = pb.w;
        } else {
            *(float4*)&Bs[0][brow][bcol] = pb;
        }
    }
    __syncthreads();

    for (int t = 0; t < nT; t++) {
        float4 pa, pb;
        if (t + 1 < nT) {
            // prefetch tile t+1 from global into registers
            pa = *(const float4*)(Ag + (size_t)(t + 1) * BK);
            pb = TRB ? *(const float4*)(Bg + (size_t)(t + 1) * BK)
                     : *(const float4*)(Bg + (size_t)(t + 1) * BK * ldb);
        }

        const float* Asb = &As[t & 1][0][0];
        const float* Bsb = &Bs[t & 1][0][0];
#pragma unroll
        for (int kk = 0; kk < BK; kk++) {
            float4 a0 = *(const float4*)(Asb + kk * SPAD + ty * 8);
            float4 a1 = *(const float4*)(Asb + kk * SPAD + ty * 8 + 4);
            float4 b0 = *(const float4*)(Bsb + kk * SPAD + tx * 8);
            float4 b1 = *(const float4*)(Bsb + kk * SPAD + tx * 8 + 4);
            float a[8] = {a0.x, a0.y, a0.z, a0.w, a1.x, a1.y, a1.z, a1.w};
            float b[8] = {b0.x, b0.y, b0.z, b0.w, b1.x, b1.y, b1.z, b1.w};
#pragma unroll
            for (int i = 0; i < 8; i++)
#pragma unroll
                for (int j = 0; j < 8; j++)
                    acc[i][j] += a[i] * b[j];
        }

        if (t + 1 < nT) {
            int nb = (t + 1) & 1;
            As[nb][aq + 0][arow] = pa.x;
            As[nb][aq + 1][arow] = pa.y;
            As[nb][aq + 2][arow] = pa.z;
            As[nb][aq + 3][arow] = pa.w;
            if (TRB) {
                Bs[nb][bq + 0][bn] = pb.x;
                Bs[nb][bq + 1][bn] = pb.y;
                Bs[nb][bq + 2][bn] = pb.z;
                Bs[nb][bq + 3][bn] = pb.w;
            } else {
                *(float4*)&Bs[nb][brow][bcol] = pb;
            }
            __syncthreads();
        }
    }

#pragma unroll
    for (int i = 0; i < 8; i++) {
        size_t roff = (size_t)(rowBase + ty * 8 + i) * ldc + colBase + tx * 8;
#pragma unroll
        for (int v = 0; v < 2; v++) {
            float4 val;
            val.x = acc[i][v * 4 + 0] * alpha;
            val.y = acc[i][v * 4 + 1] * alpha;
            val.z = acc[i][v * 4 + 2] * alpha;
            val.w = acc[i][v * 4 + 3] * alpha;
            if (bias) {
                float4 bv = *(const float4*)&bias[colBase + tx * 8 + v * 4];
                val.x += bv.x; val.y += bv.y; val.z += bv.z; val.w += bv.w;
            }
            if (ACC) {
                float4 old = *(float4*)&C[roff + v * 4];
                val.x += old.x; val.y += old.y; val.z += old.z; val.w += old.w;
            }
            *(float4*)&C[roff + v * 4] = val;
        }
    }
}

template<bool ACC, bool TRB>
static void G(const float* A, int lda, long aB, long aH,
              const float* Bm, int ldb, long bB, long bH,
              float* C, int ldc, long cB, long cH,
              int M, int N, int K, int Z, int nH, float alpha, const float* bias)
{
    dim3 grid(N / BN, M / BM, Z);
    gemm_k<ACC, TRB><<<grid, 256>>>(A, lda, aB, aH, Bm, ldb, bB, bH,
                                    C, ldc, cB, cH, K, nH, alpha, bias);
}

// ---------------- row softmax (row length 1024, one pass in registers) ----------------
__global__ __launch_bounds__(256) void softmax_k(float* __restrict__ S)
{
    float4* row = (float4*)(S + (size_t)blockIdx.x * 1024);
    int tid = threadIdx.x;
    __shared__ float red[8];

    float4 v = row[tid];
    float m = fmaxf(fmaxf(v.x, v.y), fmaxf(v.z, v.w));
#pragma unroll
    for (int o = 16; o; o >>= 1) m = fmaxf(m, __shfl_xor_sync(0xffffffffu, m, o));
    if ((tid & 31) == 0) red[tid >> 5] = m;
    __syncthreads();
    if (tid < 8) {
        float t = red[tid];
#pragma unroll
        for (int o = 4; o; o >>= 1) t = fmaxf(t, __shfl_xor_sync(0xffu, t, o));
        red[tid] = t;
    }
    __syncthreads();
    m = red[0];

    v.x = __expf(v.x - m); v.y = __expf(v.y - m);
    v.z = __expf(v.z - m); v.w = __expf(v.w - m);
    float s = v.x + v.y + v.z + v.w;
#pragma unroll
    for (int o = 16; o; o >>= 1) s += __shfl_xor_sync(0xffffffffu, s, o);
    __syncthreads();
    if ((tid & 31) == 0) red[tid >> 5] = s;
    __syncthreads();
    if (tid < 8) {
        float t = red[tid];
#pragma unroll
        for (int o = 4; o; o >>= 1) t += __shfl_xor_sync(0xffu, t, o);
        red[tid] = t;
    }
    __syncthreads();
    float inv = 1.f / red[0];
    v.x *= inv; v.y *= inv; v.z *= inv; v.w *= inv;
    row[tid] = v;
}

// ---------------- out = LayerNorm(t + res) * g + b  (row length CH) ----------------
__global__ void add_ln_k(const float* __restrict__ t, const float* __restrict__ res,
                         const float* __restrict__ g, const float* __restrict__ b,
                         float* __restrict__ out)
{
    __shared__ float buf[CH];
    __shared__ float red[256];
    size_t off = (size_t)blockIdx.x * CH;
    int tid = threadIdx.x;
    float s = 0.f;
    for (int i = tid; i < CH; i += 256) { float y = t[off + i] + res[off + i]; buf[i] = y; s += y; }
    red[tid] = s; __syncthreads();
    for (int st = 128; st; st >>= 1) { if (tid < st) red[tid] += red[tid + st]; __syncthreads(); }
    float mean = red[0] * (1.f / CH);
    __syncthreads();
    float v = 0.f;
    for (int i = tid; i < CH; i += 256) { float d = buf[i] - mean; v += d * d; }
    red[tid] = v; __syncthreads();
    for (int st = 128; st; st >>= 1) { if (tid < st) red[tid] += red[tid + st]; __syncthreads(); }
    float rstd = rsqrtf(red[0] * (1.f / CH) + 1e-5f);
    for (int i = tid; i < CH; i += 256) out[off + i] = (buf[i] - mean) * rstd * g[i] + b[i];
}

// ---------------- input projections ----------------
__global__ void proj_in_k(const float* __restrict__ cx, const float* __restrict__ cy,
                          const float* __restrict__ W, const float* __restrict__ b,
                          float* __restrict__ out, int dom)
{
    int idx = blockIdx.x * blockDim.x + threadIdx.x;
    int j = idx & (CH - 1);
    int bn = idx >> 9;
    float x0 = cx[bn];
    const float* y = cy + (size_t)bn * 8 + dom * 2;
    out[idx] = fmaf(x0, W[j], fmaf(y[0], W[CH + j], fmaf(y[1], W[2 * CH + j], b[j])));
}

__global__ void proj1_k(const float* __restrict__ x, const float* __restrict__ W,
                        const float* __restrict__ b, float* __restrict__ out)
{
    int idx = blockIdx.x * blockDim.x + threadIdx.x;
    int j = idx & (CH - 1);
    int i = idx >> 9;
    out[idx] = fmaf(x[i], W[j], b[j]);
}

// ---------------- orchestration ----------------
extern "C" void kernel_launch(void* const* d_in, const int* in_sizes, int n_in,
                              void* d_out, int out_size)
{
    const float* cx    = (const float*)d_in[0];
    const float* cy    = (const float*)d_in[1];
    const float* txp   = (const float*)d_in[2];
    const float* in_W  = (const float*)d_in[3];
    const float* in_b  = (const float*)d_in[4];
    const float* cx_W  = (const float*)d_in[5];
    const float* cx_b  = (const float*)d_in[6];
    const float* tx_W  = (const float*)d_in[7];
    const float* tx_b  = (const float*)d_in[8];
    const float* sc_Wk = (const float*)d_in[9];
    const float* sc_Wv = (const float*)d_in[10];
    const float* sc_Wq = (const float*)d_in[11];
    const float* sc_Wf = (const float*)d_in[12];
    const float* sc_bf = (const float*)d_in[13];
    const float* sc_g  = (const float*)d_in[14];
    const float* sc_b  = (const float*)d_in[15];
    const float* ca_Wk = (const float*)d_in[16];
    const float* ca_Wv = (const float*)d_in[17];
    const float* ca_Wq = (const float*)d_in[18];
    const float* ca_Wf = (const float*)d_in[19];
    const float* ca_bf = (const float*)d_in[20];
    const float* ca_g  = (const float*)d_in[21];
    const float* ca_b  = (const float*)d_in[22];

    void* p;
    cudaGetSymbolAddress(&p, g_e);  float* e   = (float*)p;
    cudaGetSymbolAddress(&p, g_e1); float* e1b = (float*)p;
    cudaGetSymbolAddress(&p, g_e2); float* e2b = (float*)p;
    cudaGetSymbolAddress(&p, g_e3); float* e3b = (float*)p;
    cudaGetSymbolAddress(&p, g_K);  float* Kb  = (float*)p;
    cudaGetSymbolAddress(&p, g_V);  float* Vb  = (float*)p;
    cudaGetSymbolAddress(&p, g_Q);  float* Qb  = (float*)p;
    cudaGetSymbolAddress(&p, g_K2); float* K2b = (float*)p;
    cudaGetSymbolAddress(&p, g_V2); float* V2b = (float*)p;
    cudaGetSymbolAddress(&p, g_Q2); float* Q2b = (float*)p;
    cudaGetSymbolAddress(&p, g_r);  float* rb  = (float*)p;
    cudaGetSymbolAddress(&p, g_t);  float* tb  = (float*)p;
    cudaGetSymbolAddress(&p, g_q);  float* qb  = (float*)p;
    cudaGetSymbolAddress(&p, g_k0); float* k0b = (float*)p;
    cudaGetSymbolAddress(&p, g_S);  float* Sb  = (float*)p;

    const int totE = CB * CN * CH;

    proj_in_k<<<totE / 256, 256>>>(cx, cy, in_W, in_b, e,   0);
    proj_in_k<<<totE / 256, 256>>>(cx, cy, in_W, in_b, e1b, 1);
    proj_in_k<<<totE / 256, 256>>>(cx, cy, in_W, in_b, e2b, 2);
    proj_in_k<<<totE / 256, 256>>>(cx, cy, in_W, in_b, e3b, 3);
    proj1_k<<<(CB * CM * CH) / 256, 256>>>(txp, tx_W, tx_b, qb);
    proj1_k<<<totE / 256, 256>>>(cx, cx_W, cx_b, k0b);

    auto sc_layer = [&](const float* x2, bool self, int i) {
        const float* Wk = sc_Wk + (size_t)i * CH * CH;
        const float* Wv = sc_Wv + (size_t)i * CH * CH;
        const float* Wq = sc_Wq + (size_t)i * CH * CH;
        const float* Wf = sc_Wf + (size_t)i * 2 * CH * CH;
        const float* bf = sc_bf + (size_t)i * CH;
        const float* lg = sc_g  + (size_t)i * CH;
        const float* lb = sc_b  + (size_t)i * CH;
        const int R = CB * CN;
        G<false, false>(e, CH, 0, 0, Wk, CH, 0, 0, Kb, CH, 0, 0, R, CH, CH, 1, 1, 1.f, nullptr);
        G<false, false>(e, CH, 0, 0, Wv, CH, 0, 0, Vb, CH, 0, 0, R, CH, CH, 1, 1, 1.f, nullptr);
        G<false, false>(e, CH, 0, 0, Wq, CH, 0, 0, Qb, CH, 0, 0, R, CH, CH, 1, 1, 1.f, nullptr);
        if (!self) {
            G<false, false>(x2, CH, 0, 0, Wk, CH, 0, 0, K2b, CH, 0, 0, R, CH, CH, 1, 1, 1.f, nullptr);
            G<false, false>(x2, CH, 0, 0, Wv, CH, 0, 0, V2b, CH, 0, 0, R, CH, CH, 1, 1, 1.f, nullptr);
            G<false, false>(x2, CH, 0, 0, Wq, CH, 0, 0, Q2b, CH, 0, 0, R, CH, CH, 1, 1, 1.f, nullptr);
        }
        const int d = 256, h = 2, Z = CB * h;
        const float* Qs[4] = {Qb, Q2b, Q2b, Qb};
        const float* Ks[4] = {Kb, K2b, Kb, K2b};
        const float* Vs[4] = {Vb, V2b, Vb, V2b};
        int nT = self ? 1 : 4;
        for (int t = 0; t < nT; t++) {
            G<false, true>(Qs[t], CH, (long)CN * CH, d, Ks[t], CH, (long)CN * CH, d,
                           Sb, CN, (long)h * CN * CN, (long)CN * CN,
                           CN, CN, d, Z, h, 0.0625f, nullptr);  // 1/sqrt(256)
            softmax_k<<<Z * CN, 256>>>(Sb);
            float ao = self ? 4.f : 1.f;
            if (t == 0)
                G<false, false>(Sb, CN, (long)h * CN * CN, (long)CN * CN, Vs[t], CH, (long)CN * CH, d,
                                rb, CH, (long)CN * CH, d, CN, d, CN, Z, h, ao, nullptr);
            else
                G<true, false>(Sb, CN, (long)h * CN * CN, (long)CN * CN, Vs[t], CH, (long)CN * CH, d,
                               rb, CH, (long)CN * CH, d, CN, d, CN, Z, h, 1.f, nullptr);
        }
        G<false, false>(e,  CH, 0, 0, Wf,            CH, 0, 0, tb, CH, 0, 0, R, CH, CH, 1, 1, 1.f, bf);
        G<true,  false>(rb, CH, 0, 0, Wf + CH * CH,  CH, 0, 0, tb, CH, 0, 0, R, CH, CH, 1, 1, 1.f, nullptr);
        add_ln_k<<<R, 256>>>(tb, e, lg, lb, e);
    };

    sc_layer(e,   true,  0); sc_layer(e,   true,  1);
    sc_layer(e1b, false, 0); sc_layer(e1b, false, 1);
    sc_layer(e2b, false, 0); sc_layer(e2b, false, 1);
    sc_layer(e3b, false, 0); sc_layer(e3b, false, 1);

    for (int i = 0; i < 2; i++) {
        const float* Wk = ca_Wk + (size_t)i * CH * CH;
        const float* Wv = ca_Wv + (size_t)i * CH * CH;
        const float* Wq = ca_Wq + (size_t)i * CH * CH;
        const float* Wf = ca_Wf + (size_t)i * 2 * CH * CH;
        const float* bf = ca_bf + (size_t)i * CH;
        const float* lg = ca_g  + (size_t)i * CH;
        const float* lb = ca_b  + (size_t)i * CH;
        const int R = CB * CM;
        G<false, false>(k0b, CH, 0, 0, Wk, CH, 0, 0, Kb, CH, 0, 0, CB * CN, CH, CH, 1, 1, 1.f, nullptr);
        G<false, false>(e,   CH, 0, 0, Wv, CH, 0, 0, Vb, CH, 0, 0, CB * CN, CH, CH, 1, 1, 1.f, nullptr);
        G<false, false>(qb,  CH, 0, 0, Wq, CH, 0, 0, Qb, CH, 0, 0, R,       CH, CH, 1, 1, 1.f, nullptr);
        const int d = 128, h = 4, Z = CB * h;
        G<false, true>(Qb, CH, (long)CM * CH, d, Kb, CH, (long)CN * CH, d,
                       Sb, CN, (long)h * CM * CN, (long)CM * CN,
                       CM, CN, d, Z, h, 0.0883883476483184f, nullptr);  // 1/sqrt(128)
        softmax_k<<<Z * CM, 256>>>(Sb);
        G<false, false>(Sb, CN, (long)h * CM * CN, (long)CM * CN, Vb, CH, (long)CN * CH, d,
                        rb, CH, (long)CM * CH, d, CM, d, CN, Z, h, 1.f, nullptr);
        G<false, false>(qb, CH, 0, 0, Wf,           CH, 0, 0, tb, CH, 0, 0, R, CH, CH, 1, 1, 1.f, bf);
        G<true,  false>(rb, CH, 0, 0, Wf + CH * CH, CH, 0, 0, tb, CH, 0, 0, R, CH, CH, 1, 1, 1.f, nullptr);
        add_ln_k<<<R, 256>>>(tb, qb, lg, lb, (i == 1) ? (float*)d_out : qb);
    }
}

// round 7
// speedup vs baseline: 2.1775x; 1.6133x over previous
#include <cuda_runtime.h>
#include <cuda_bf16.h>
#include <math.h>
#include <stdint.h>

#define CB 4
#define CN 1024
#define CM 1024
#define CH 512

// ---------------- scratch (device globals; no allocation allowed) ----------------
__device__ __align__(16) float g_e  [CB*CN*CH];
__device__ __align__(16) float g_e1 [CB*CN*CH];
__device__ __align__(16) float g_e2 [CB*CN*CH];
__device__ __align__(16) float g_e3 [CB*CN*CH];
__device__ __align__(16) float g_K  [CB*CN*CH];
__device__ __align__(16) float g_V  [CB*CN*CH];
__device__ __align__(16) float g_Q  [CB*CN*CH];
__device__ __align__(16) float g_K2 [CB*CN*CH];
__device__ __align__(16) float g_V2 [CB*CN*CH];
__device__ __align__(16) float g_Q2 [CB*CN*CH];
__device__ __align__(16) float g_r  [CB*CN*CH];
__device__ __align__(16) float g_t  [CB*CN*CH];
__device__ __align__(16) float g_q  [CB*CM*CH];
__device__ __align__(16) float g_k0 [CB*CN*CH];
__device__ __align__(16) float g_S  [16u*1024u*1024u];
__device__ __align__(16) float g_WT [4*1310720];      // transposed weights: [sc0][sc1][ca0][ca1]
__device__ __align__(16) float g_VT [CB*CH*CN];       // V^T per batch
__device__ __align__(16) float g_VT2[CB*CH*CN];

// ---------------- bf16 split helpers ----------------
static __device__ __forceinline__ unsigned short bfbits(__nv_bfloat16 h){
    return reinterpret_cast<unsigned short&>(h);
}
// float4 -> 4 bf16 hi bits + 4 bf16 lo bits (x = hi + lo)
static __device__ __forceinline__ void split4(float4 v, unsigned long long& hi64, unsigned long long& lo64){
    __nv_bfloat16 h0 = __float2bfloat16(v.x);
    __nv_bfloat16 h1 = __float2bfloat16(v.y);
    __nv_bfloat16 h2 = __float2bfloat16(v.z);
    __nv_bfloat16 h3 = __float2bfloat16(v.w);
    __nv_bfloat16 l0 = __float2bfloat16(v.x - __bfloat162float(h0));
    __nv_bfloat16 l1 = __float2bfloat16(v.y - __bfloat162float(h1));
    __nv_bfloat16 l2 = __float2bfloat16(v.z - __bfloat162float(h2));
    __nv_bfloat16 l3 = __float2bfloat16(v.w - __bfloat162float(h3));
    hi64 = (unsigned long long)bfbits(h0) | ((unsigned long long)bfbits(h1) << 16)
         | ((unsigned long long)bfbits(h2) << 32) | ((unsigned long long)bfbits(h3) << 48);
    lo64 = (unsigned long long)bfbits(l0) | ((unsigned long long)bfbits(l1) << 16)
         | ((unsigned long long)bfbits(l2) << 32) | ((unsigned long long)bfbits(l3) << 48);
}

static __device__ __forceinline__ void mma16816(float* c, const uint32_t* a, const uint32_t* b){
    asm volatile(
        "mma.sync.aligned.m16n8k16.row.col.f32.bf16.bf16.f32 "
        "{%0,%1,%2,%3}, {%4,%5,%6,%7}, {%8,%9}, {%0,%1,%2,%3};"
        : "+f"(c[0]), "+f"(c[1]), "+f"(c[2]), "+f"(c[3])
        : "r"(a[0]), "r"(a[1]), "r"(a[2]), "r"(a[3]), "r"(b[0]), "r"(b[1]));
}

// ---------------- mma.sync 3xBF16 batched GEMM ----------------
// C[M,N] = alpha * A[M,K] @ B[N,K]^T  [+ bias] [+ C]   (both operands K-major fp32)
// CTA tile 128(M) x 64(N), BK=32. 8 warps = 4(m) x 2(n); warp tile 32x32.
// smem (words of u32, stride 20 per row = 40 bf16 = conflict-free):
//   stage s: A_hi[128*20] | A_lo[128*20] | B_hi[64*20] | B_lo[64*20]  = 7680 words
#define SAW 20
#define STG_W 7680
#define SMEM_DYN (2*STG_W*4)

template<bool ACC>
__global__ __launch_bounds__(256, 2) void tgemm(
    const float* __restrict__ A, int lda, long aB, long aH,
    const float* __restrict__ Bm, int ldb, long bB, long bH,
    float* __restrict__ C, int ldc, long cB, long cH,
    int K, int nH, float alpha, const float* __restrict__ bias)
{
    extern __shared__ uint32_t sm32[];

    int z = blockIdx.z;
    int bb = z / nH, hh = z - bb * nH;
    A  += (size_t)bb * aB + (size_t)hh * aH;
    Bm += (size_t)bb * bB + (size_t)hh * bH;
    C  += (size_t)bb * cB + (size_t)hh * cH;

    int tid = threadIdx.x, wid = tid >> 5, L = tid & 31;
    int rowBase = blockIdx.y * 128, colBase = blockIdx.x * 64;

    int mwarp = (wid >> 1) * 32;       // 0,32,64,96
    int nwarp = (wid & 1) * 32;        // 0,32
    int qrow = L >> 2, qk = L & 3;

    // global load mapping
    int arow = tid >> 1, akoff = (tid & 1) * 16;           // A: 4 float4 per thread
    int brow = tid >> 2, bkoff = (tid & 3) * 8;            // B: 2 float4 per thread
    const float* Ag = A  + (size_t)(rowBase + arow) * lda + akoff;
    const float* Bg = Bm + (size_t)(colBase + brow) * ldb + bkoff;

    float acc[2][4][4];
#pragma unroll
    for (int mt = 0; mt < 2; mt++)
#pragma unroll
        for (int nt = 0; nt < 4; nt++)
#pragma unroll
            for (int j = 0; j < 4; j++) acc[mt][nt][j] = 0.f;

    const int nC = K / 32;

    // store helper offsets (word index): A word = row*SAW + k/2
    auto storeChunk = [&](int buf, float4 va[4], float4 vb[2]) {
        uint32_t* st = sm32 + buf * STG_W;
        unsigned long long hv, lv;
#pragma unroll
        for (int j = 0; j < 4; j++) {
            int w = arow * SAW + (akoff >> 1) + j * 2;
            split4(va[j], hv, lv);
            *(unsigned long long*)(st + w)            = hv;
            *(unsigned long long*)(st + 2560 + w)     = lv;
        }
#pragma unroll
        for (int j = 0; j < 2; j++) {
            int w = brow * SAW + (bkoff >> 1) + j * 2;
            split4(vb[j], hv, lv);
            *(unsigned long long*)(st + 5120 + w)     = hv;
            *(unsigned long long*)(st + 6400 + w)     = lv;
        }
    };

    // prologue: chunk 0
    {
        float4 va[4], vb[2];
#pragma unroll
        for (int j = 0; j < 4; j++) va[j] = *(const float4*)(Ag + j * 4);
#pragma unroll
        for (int j = 0; j < 2; j++) vb[j] = *(const float4*)(Bg + j * 4);
        storeChunk(0, va, vb);
    }
    __syncthreads();

#pragma unroll 1
    for (int c = 0; c < nC; c++) {
        float4 va[4], vb[2];
        bool more = (c + 1 < nC);
        if (more) {
            const float* pa = Ag + (size_t)(c + 1) * 32;
            const float* pb = Bg + (size_t)(c + 1) * 32;
#pragma unroll
            for (int j = 0; j < 4; j++) va[j] = *(const float4*)(pa + j * 4);
#pragma unroll
            for (int j = 0; j < 2; j++) vb[j] = *(const float4*)(pb + j * 4);
        }

        const uint32_t* sa = sm32 + (c & 1) * STG_W;
        const uint32_t* sb = sa + 5120;
#pragma unroll
        for (int ksw = 0; ksw < 16; ksw += 8) {     // two k16 steps (word offset 0, 8)
            uint32_t ah[2][4], al[2][4], bh[4][2], bl[4][2];
#pragma unroll
            for (int mt = 0; mt < 2; mt++) {
                int r0 = (mwarp + mt * 16 + qrow) * SAW + ksw + qk;
                int r1 = r0 + 8 * SAW;
                ah[mt][0] = sa[r0];        ah[mt][1] = sa[r1];
                ah[mt][2] = sa[r0 + 4];    ah[mt][3] = sa[r1 + 4];
                al[mt][0] = sa[2560 + r0];     al[mt][1] = sa[2560 + r1];
                al[mt][2] = sa[2560 + r0 + 4]; al[mt][3] = sa[2560 + r1 + 4];
            }
#pragma unroll
            for (int nt = 0; nt < 4; nt++) {
                int w = (nwarp + nt * 8 + qrow) * SAW + ksw + qk;
                bh[nt][0] = sb[w];        bh[nt][1] = sb[w + 4];
                bl[nt][0] = sb[1280 + w]; bl[nt][1] = sb[1280 + w + 4];
            }
#pragma unroll
            for (int mt = 0; mt < 2; mt++)
#pragma unroll
                for (int nt = 0; nt < 4; nt++) {
                    mma16816(acc[mt][nt], ah[mt], bh[nt]);
                    mma16816(acc[mt][nt], ah[mt], bl[nt]);
                    mma16816(acc[mt][nt], al[mt], bh[nt]);
                }
        }

        if (more) storeChunk((c + 1) & 1, va, vb);
        __syncthreads();
    }

    // epilogue
#pragma unroll
    for (int mt = 0; mt < 2; mt++) {
        int row0 = rowBase + mwarp + mt * 16 + qrow;
#pragma unroll
        for (int nt = 0; nt < 4; nt++) {
            int col = colBase + nwarp + nt * 8 + qk * 2;
            float2 v0 = make_float2(acc[mt][nt][0] * alpha, acc[mt][nt][1] * alpha);
            float2 v1 = make_float2(acc[mt][nt][2] * alpha, acc[mt][nt][3] * alpha);
            if (bias) {
                float2 bv = *(const float2*)&bias[col];
                v0.x += bv.x; v0.y += bv.y;
                v1.x += bv.x; v1.y += bv.y;
            }
            size_t o0 = (size_t)row0 * ldc + col;
            size_t o1 = (size_t)(row0 + 8) * ldc + col;
            if (ACC) {
                float2 a0 = *(const float2*)&C[o0];
                float2 a1 = *(const float2*)&C[o1];
                v0.x += a0.x; v0.y += a0.y;
                v1.x += a1.x; v1.y += a1.y;
            }
            *(float2*)&C[o0] = v0;
            *(float2*)&C[o1] = v1;
        }
    }
}

template<bool ACC>
static void G(const float* A, int lda, long aB, long aH,
              const float* Bm, int ldb, long bB, long bH,
              float* C, int ldc, long cB, long cH,
              int M, int N, int K, int Z, int nH, float alpha, const float* bias)
{
    dim3 grid(N / 64, M / 128, Z);
    tgemm<ACC><<<grid, 256, SMEM_DYN>>>(A, lda, aB, aH, Bm, ldb, bB, bH,
                                        C, ldc, cB, cH, K, nH, alpha, bias);
}

// ---------------- batched transpose: out[z][c][r] = in[z][r][c], R,C mult of 32 ----------------
__global__ void transpose_k(const float* __restrict__ in, float* __restrict__ out, int R, int Cc)
{
    __shared__ float t[32][33];
    size_t zoff = (size_t)blockIdx.z * R * Cc;
    in += zoff; out += zoff;
    int c0 = blockIdx.x * 32, r0 = blockIdx.y * 32;
    int x = threadIdx.x, y = threadIdx.y;
#pragma unroll
    for (int j = 0; j < 32; j += 8) t[y + j][x] = in[(size_t)(r0 + y + j) * Cc + c0 + x];
    __syncthreads();
#pragma unroll
    for (int j = 0; j < 32; j += 8) out[(size_t)(c0 + y + j) * R + r0 + x] = t[x][y + j];
}

// ---------------- row softmax (row length 1024, one pass in registers) ----------------
__global__ __launch_bounds__(256) void softmax_k(float* __restrict__ S)
{
    float4* row = (float4*)(S + (size_t)blockIdx.x * 1024);
    int tid = threadIdx.x;
    __shared__ float red[8];

    float4 v = row[tid];
    float m = fmaxf(fmaxf(v.x, v.y), fmaxf(v.z, v.w));
#pragma unroll
    for (int o = 16; o; o >>= 1) m = fmaxf(m, __shfl_xor_sync(0xffffffffu, m, o));
    if ((tid & 31) == 0) red[tid >> 5] = m;
    __syncthreads();
    if (tid < 8) {
        float t = red[tid];
#pragma unroll
        for (int o = 4; o; o >>= 1) t = fmaxf(t, __shfl_xor_sync(0xffu, t, o));
        red[tid] = t;
    }
    __syncthreads();
    m = red[0];

    v.x = __expf(v.x - m); v.y = __expf(v.y - m);
    v.z = __expf(v.z - m); v.w = __expf(v.w - m);
    float s = v.x + v.y + v.z + v.w;
#pragma unroll
    for (int o = 16; o; o >>= 1) s += __shfl_xor_sync(0xffffffffu, s, o);
    __syncthreads();
    if ((tid & 31) == 0) red[tid >> 5] = s;
    __syncthreads();
    if (tid < 8) {
        float t = red[tid];
#pragma unroll
        for (int o = 4; o; o >>= 1) t += __shfl_xor_sync(0xffu, t, o);
        red[tid] = t;
    }
    __syncthreads();
    float inv = 1.f / red[0];
    v.x *= inv; v.y *= inv; v.z *= inv; v.w *= inv;
    row[tid] = v;
}

// ---------------- out = LayerNorm(t + res) * g + b  (row length CH) ----------------
__global__ void add_ln_k(const float* __restrict__ t, const float* __restrict__ res,
                         const float* __restrict__ g, const float* __restrict__ b,
                         float* __restrict__ out)
{
    __shared__ float buf[CH];
    __shared__ float red[256];
    size_t off = (size_t)blockIdx.x * CH;
    int tid = threadIdx.x;
    float s = 0.f;
    for (int i = tid; i < CH; i += 256) { float y = t[off + i] + res[off + i]; buf[i] = y; s += y; }
    red[tid] = s; __syncthreads();
    for (int st = 128; st; st >>= 1) { if (tid < st) red[tid] += red[tid + st]; __syncthreads(); }
    float mean = red[0] * (1.f / CH);
    __syncthreads();
    float v = 0.f;
    for (int i = tid; i < CH; i += 256) { float d = buf[i] - mean; v += d * d; }
    red[tid] = v; __syncthreads();
    for (int st = 128; st; st >>= 1) { if (tid < st) red[tid] += red[tid + st]; __syncthreads(); }
    float rstd = rsqrtf(red[0] * (1.f / CH) + 1e-5f);
    for (int i = tid; i < CH; i += 256) out[off + i] = (buf[i] - mean) * rstd * g[i] + b[i];
}

// ---------------- input projections ----------------
__global__ void proj_in_k(const float* __restrict__ cx, const float* __restrict__ cy,
                          const float* __restrict__ W, const float* __restrict__ b,
                          float* __restrict__ out, int dom)
{
    int idx = blockIdx.x * blockDim.x + threadIdx.x;
    int j = idx & (CH - 1);
    int bn = idx >> 9;
    float x0 = cx[bn];
    const float* y = cy + (size_t)bn * 8 + dom * 2;
    out[idx] = fmaf(x0, W[j], fmaf(y[0], W[CH + j], fmaf(y[1], W[2 * CH + j], b[j])));
}

__global__ void proj1_k(const float* __restrict__ x, const float* __restrict__ W,
                        const float* __restrict__ b, float* __restrict__ out)
{
    int idx = blockIdx.x * blockDim.x + threadIdx.x;
    int j = idx & (CH - 1);
    int i = idx >> 9;
    out[idx] = fmaf(x[i], W[j], b[j]);
}

// ---------------- orchestration ----------------
extern "C" void kernel_launch(void* const* d_in, const int* in_sizes, int n_in,
                              void* d_out, int out_size)
{
    const float* cx    = (const float*)d_in[0];
    const float* cy    = (const float*)d_in[1];
    const float* txp   = (const float*)d_in[2];
    const float* in_W  = (const float*)d_in[3];
    const float* in_b  = (const float*)d_in[4];
    const float* cx_W  = (const float*)d_in[5];
    const float* cx_b  = (const float*)d_in[6];
    const float* tx_W  = (const float*)d_in[7];
    const float* tx_b  = (const float*)d_in[8];
    const float* sc_Wk = (const float*)d_in[9];
    const float* sc_Wv = (const float*)d_in[10];
    const float* sc_Wq = (const float*)d_in[11];
    const float* sc_Wf = (const float*)d_in[12];
    const float* sc_bf = (const float*)d_in[13];
    const float* sc_g  = (const float*)d_in[14];
    const float* sc_b  = (const float*)d_in[15];
    const float* ca_Wk = (const float*)d_in[16];
    const float* ca_Wv = (const float*)d_in[17];
    const float* ca_Wq = (const float*)d_in[18];
    const float* ca_Wf = (const float*)d_in[19];
    const float* ca_bf = (const float*)d_in[20];
    const float* ca_g  = (const float*)d_in[21];
    const float* ca_b  = (const float*)d_in[22];

    cudaFuncSetAttribute(tgemm<false>, cudaFuncAttributeMaxDynamicSharedMemorySize, SMEM_DYN);
    cudaFuncSetAttribute(tgemm<true>,  cudaFuncAttributeMaxDynamicSharedMemorySize, SMEM_DYN);

    void* p;
    cudaGetSymbolAddress(&p, g_e);  float* e   = (float*)p;
    cudaGetSymbolAddress(&p, g_e1); float* e1b = (float*)p;
    cudaGetSymbolAddress(&p, g_e2); float* e2b = (float*)p;
    cudaGetSymbolAddress(&p, g_e3); float* e3b = (float*)p;
    cudaGetSymbolAddress(&p, g_K);  float* Kb  = (float*)p;
    cudaGetSymbolAddress(&p, g_V);  float* Vb  = (float*)p;
    cudaGetSymbolAddress(&p, g_Q);  float* Qb  = (float*)p;
    cudaGetSymbolAddress(&p, g_K2); float* K2b = (float*)p;
    cudaGetSymbolAddress(&p, g_V2); float* V2b = (float*)p;
    cudaGetSymbolAddress(&p, g_Q2); float* Q2b = (float*)p;
    cudaGetSymbolAddress(&p, g_r);  float* rb  = (float*)p;
    cudaGetSymbolAddress(&p, g_t);  float* tb  = (float*)p;
    cudaGetSymbolAddress(&p, g_q);  float* qb  = (float*)p;
    cudaGetSymbolAddress(&p, g_k0); float* k0b = (float*)p;
    cudaGetSymbolAddress(&p, g_S);  float* Sb  = (float*)p;
    cudaGetSymbolAddress(&p, g_WT); float* WT  = (float*)p;
    cudaGetSymbolAddress(&p, g_VT); float* VT  = (float*)p;
    cudaGetSymbolAddress(&p, g_VT2);float* VT2 = (float*)p;

    const int totE = CB * CN * CH;

    // ---- transpose all weights once (B operands must be (N,K) K-major) ----
    const long WSET = 1310720;                 // 3*512*512 + 512*1024 floats per layer set
    auto wslot = [&](int grp, int i, int which) -> float* {
        float* base = WT + (grp * 2 + i) * WSET;
        if (which < 3) return base + (long)which * 262144;
        return base + 786432;
    };
    {
        dim3 tb32(32, 8);
        for (int i = 0; i < 2; i++) {
            transpose_k<<<dim3(16, 16, 1), tb32>>>(sc_Wk + (size_t)i * 262144, wslot(0, i, 0), 512, 512);
            transpose_k<<<dim3(16, 16, 1), tb32>>>(sc_Wv + (size_t)i * 262144, wslot(0, i, 1), 512, 512);
            transpose_k<<<dim3(16, 16, 1), tb32>>>(sc_Wq + (size_t)i * 262144, wslot(0, i, 2), 512, 512);
            transpose_k<<<dim3(16, 32, 1), tb32>>>(sc_Wf + (size_t)i * 524288, wslot(0, i, 3), 1024, 512);
            transpose_k<<<dim3(16, 16, 1), tb32>>>(ca_Wk + (size_t)i * 262144, wslot(1, i, 0), 512, 512);
            transpose_k<<<dim3(16, 16, 1), tb32>>>(ca_Wv + (size_t)i * 262144, wslot(1, i, 1), 512, 512);
            transpose_k<<<dim3(16, 16, 1), tb32>>>(ca_Wq + (size_t)i * 262144, wslot(1, i, 2), 512, 512);
            transpose_k<<<dim3(16, 32, 1), tb32>>>(ca_Wf + (size_t)i * 524288, wslot(1, i, 3), 1024, 512);
        }
    }

    proj_in_k<<<totE / 256, 256>>>(cx, cy, in_W, in_b, e,   0);
    proj_in_k<<<totE / 256, 256>>>(cx, cy, in_W, in_b, e1b, 1);
    proj_in_k<<<totE / 256, 256>>>(cx, cy, in_W, in_b, e2b, 2);
    proj_in_k<<<totE / 256, 256>>>(cx, cy, in_W, in_b, e3b, 3);
    proj1_k<<<(CB * CM * CH) / 256, 256>>>(txp, tx_W, tx_b, qb);
    proj1_k<<<totE / 256, 256>>>(cx, cx_W, cx_b, k0b);

    auto transV = [&](const float* src, float* dst) {
        transpose_k<<<dim3(CH / 32, CN / 32, CB), dim3(32, 8)>>>(src, dst, CN, CH);
    };

    auto sc_layer = [&](const float* x2, bool self, int i) {
        const float* WkT = wslot(0, i, 0);
        const float* WvT = wslot(0, i, 1);
        const float* WqT = wslot(0, i, 2);
        const float* WfT = wslot(0, i, 3);       // 512 rows x 1024 cols (k)
        const float* bf  = sc_bf + (size_t)i * CH;
        const float* lg  = sc_g  + (size_t)i * CH;
        const float* lb  = sc_b  + (size_t)i * CH;
        const int R = CB * CN;
        G<false>(e, CH, 0, 0, WkT, CH, 0, 0, Kb, CH, 0, 0, R, CH, CH, 1, 1, 1.f, nullptr);
        G<false>(e, CH, 0, 0, WvT, CH, 0, 0, Vb, CH, 0, 0, R, CH, CH, 1, 1, 1.f, nullptr);
        G<false>(e, CH, 0, 0, WqT, CH, 0, 0, Qb, CH, 0, 0, R, CH, CH, 1, 1, 1.f, nullptr);
        transV(Vb, VT);
        if (!self) {
            G<false>(x2, CH, 0, 0, WkT, CH, 0, 0, K2b, CH, 0, 0, R, CH, CH, 1, 1, 1.f, nullptr);
            G<false>(x2, CH, 0, 0, WvT, CH, 0, 0, V2b, CH, 0, 0, R, CH, CH, 1, 1, 1.f, nullptr);
            G<false>(x2, CH, 0, 0, WqT, CH, 0, 0, Q2b, CH, 0, 0, R, CH, CH, 1, 1, 1.f, nullptr);
            transV(V2b, VT2);
        }
        const int d = 256, h = 2, Z = CB * h;
        const float* Qs[4] = {Qb, Q2b, Q2b, Qb};
        const float* Ks[4] = {Kb, K2b, Kb, K2b};
        const float* Vts[4] = {VT, VT2, VT, VT2};
        int nT = self ? 1 : 4;
        for (int t = 0; t < nT; t++) {
            G<false>(Qs[t], CH, (long)CN * CH, d, Ks[t], CH, (long)CN * CH, d,
                     Sb, CN, (long)h * CN * CN, (long)CN * CN,
                     CN, CN, d, Z, h, 0.0625f, nullptr);               // 1/sqrt(256)
            softmax_k<<<Z * CN, 256>>>(Sb);
            float ao = self ? 4.f : 1.f;
            if (t == 0)
                G<false>(Sb, CN, (long)h * CN * CN, (long)CN * CN,
                         Vts[t], CN, (long)CH * CN, (long)d * CN,
                         rb, CH, (long)CN * CH, d, CN, d, CN, Z, h, ao, nullptr);
            else
                G<true>(Sb, CN, (long)h * CN * CN, (long)CN * CN,
                        Vts[t], CN, (long)CH * CN, (long)d * CN,
                        rb, CH, (long)CN * CH, d, CN, d, CN, Z, h, 1.f, nullptr);
        }
        // t = concat(e, r) @ Wf + bf = e@Wf_top + r@Wf_bot + bf   (WfT ld=1024; bot = cols 512..1023)
        G<false>(e,  CH, 0, 0, WfT,       1024, 0, 0, tb, CH, 0, 0, R, CH, CH, 1, 1, 1.f, bf);
        G<true>( rb, CH, 0, 0, WfT + 512, 1024, 0, 0, tb, CH, 0, 0, R, CH, CH, 1, 1, 1.f, nullptr);
        add_ln_k<<<R, 256>>>(tb, e, lg, lb, e);
    };

    sc_layer(e,   true,  0); sc_layer(e,   true,  1);
    sc_layer(e1b, false, 0); sc_layer(e1b, false, 1);
    sc_layer(e2b, false, 0); sc_layer(e2b, false, 1);
    sc_layer(e3b, false, 0); sc_layer(e3b, false, 1);

    // cross attention: q = _attn(k0, e, q) twice, h=4, d=128
    for (int i = 0; i < 2; i++) {
        const float* WkT = wslot(1, i, 0);
        const float* WvT = wslot(1, i, 1);
        const float* WqT = wslot(1, i, 2);
        const float* WfT = wslot(1, i, 3);
        const float* bf  = ca_bf + (size_t)i * CH;
        const float* lg  = ca_g  + (size_t)i * CH;
        const float* lb  = ca_b  + (size_t)i * CH;
        const int R = CB * CM;
        G<false>(k0b, CH, 0, 0, WkT, CH, 0, 0, Kb, CH, 0, 0, CB * CN, CH, CH, 1, 1, 1.f, nullptr);
        G<false>(e,   CH, 0, 0, WvT, CH, 0, 0, Vb, CH, 0, 0, CB * CN, CH, CH, 1, 1, 1.f, nullptr);
        G<false>(qb,  CH, 0, 0, WqT, CH, 0, 0, Qb, CH, 0, 0, R,       CH, CH, 1, 1, 1.f, nullptr);
        transV(Vb, VT);
        const int d = 128, h = 4, Z = CB * h;
        G<false>(Qb, CH, (long)CM * CH, d, Kb, CH, (long)CN * CH, d,
                 Sb, CN, (long)h * CM * CN, (long)CM * CN,
                 CM, CN, d, Z, h, 0.0883883476483184f, nullptr);       // 1/sqrt(128)
        softmax_k<<<Z * CM, 256>>>(Sb);
        G<false>(Sb, CN, (long)h * CM * CN, (long)CM * CN,
                 VT, CN, (long)CH * CN, (long)d * CN,
                 rb, CH, (long)CM * CH, d, CM, d, CN, Z, h, 1.f, nullptr);
        G<false>(qb, CH, 0, 0, WfT,       1024, 0, 0, tb, CH, 0, 0, R, CH, CH, 1, 1, 1.f, bf);
        G<true>( rb, CH, 0, 0, WfT + 512, 1024, 0, 0, tb, CH, 0, 0, R, CH, CH, 1, 1, 1.f, nullptr);
        add_ln_k<<<R, 256>>>(tb, qb, lg, lb, (i == 1) ? (float*)d_out : qb);
    }
}

// round 12
// speedup vs baseline: 2.6507x; 1.2173x over previous
#include <cuda_runtime.h>
#include <cuda_bf16.h>
#include <math.h>
#include <stdint.h>

#define CB 4
#define CN 1024
#define CM 1024
#define CH 512
#define TOK (CB*CN)          // 4096 tokens

typedef __nv_bfloat16 bf16;

// ---------------- scratch (device globals; no allocation allowed) ----------------
// fp32 tensors (needed for residual/LN/softmax-in/concat)
__device__ __align__(16) float g_e  [TOK*CH];
__device__ __align__(16) float g_e1 [TOK*CH];
__device__ __align__(16) float g_e2 [TOK*CH];
__device__ __align__(16) float g_e3 [TOK*CH];
__device__ __align__(16) float g_S  [16u*1024u*1024u];
__device__ __align__(16) float g_t  [TOK*CH];
__device__ __align__(16) float g_q  [CB*CM*CH];
// bf16 hi/lo planes (GEMM operands)
#define TE (TOK*CH)
__device__ __align__(16) bf16 g_eh[TE],  g_el[TE];
__device__ __align__(16) bf16 g_e1h[TE], g_e1l[TE];
__device__ __align__(16) bf16 g_e2h[TE], g_e2l[TE];
__device__ __align__(16) bf16 g_e3h[TE], g_e3l[TE];
__device__ __align__(16) bf16 g_Kh[TE],  g_Kl[TE];
__device__ __align__(16) bf16 g_Qh[TE],  g_Ql[TE];
__device__ __align__(16) bf16 g_K2h[TE], g_K2l[TE];
__device__ __align__(16) bf16 g_Q2h[TE], g_Q2l[TE];
__device__ __align__(16) bf16 g_Vth[TE], g_Vtl[TE];    // [CH, TOK]
__device__ __align__(16) bf16 g_Vt2h[TE],g_Vt2l[TE];
__device__ __align__(16) bf16 g_rh[TE],  g_rl[TE];
__device__ __align__(16) bf16 g_qh[TE],  g_ql[TE];
__device__ __align__(16) bf16 g_k0h[TE], g_k0l[TE];
__device__ __align__(16) bf16 g_Sh[16u*1024u*1024u], g_Sl[16u*1024u*1024u];
__device__ __align__(16) bf16 g_Wth[4*1310720], g_Wtl[4*1310720];

// ---------------- helpers ----------------
static __device__ __forceinline__ uint32_t s2u(const void* p){
    uint32_t a;
    asm("{ .reg .u64 t; cvta.to.shared.u64 t, %1; cvt.u32.u64 %0, t; }" : "=r"(a) : "l"(p));
    return a;
}
static __device__ __forceinline__ unsigned short bfbits(bf16 h){
    return reinterpret_cast<unsigned short&>(h);
}
static __device__ __forceinline__ float b2f(uint32_t bits){     // bf16 bits -> fp32 (exact)
    return __uint_as_float(bits << 16);
}
// split two floats into packed hi u32 + lo u32 (2 bf16 each)
static __device__ __forceinline__ uint32_t packsplit(float a, float b, uint32_t& lo){
    bf16 ha = __float2bfloat16(a), hb = __float2bfloat16(b);
    bf16 la = __float2bfloat16(a - b2f(bfbits(ha)));
    bf16 lb = __float2bfloat16(b - b2f(bfbits(hb)));
    lo = (uint32_t)bfbits(la) | ((uint32_t)bfbits(lb) << 16);
    return (uint32_t)bfbits(ha) | ((uint32_t)bfbits(hb) << 16);
}
static __device__ __forceinline__ void splitstore(bf16* oh, bf16* ol, size_t idx, float v){
    bf16 h = __float2bfloat16(v);
    oh[idx] = h;
    ol[idx] = __float2bfloat16(v - b2f(bfbits(h)));
}
static __device__ __forceinline__ void mma16816(float* c, const uint32_t* a, const uint32_t* b){
    asm volatile(
        "mma.sync.aligned.m16n8k16.row.col.f32.bf16.bf16.f32 "
        "{%0,%1,%2,%3}, {%4,%5,%6,%7}, {%8,%9}, {%0,%1,%2,%3};"
        : "+f"(c[0]), "+f"(c[1]), "+f"(c[2]), "+f"(c[3])
        : "r"(a[0]), "r"(a[1]), "r"(a[2]), "r"(a[3]), "r"(b[0]), "r"(b[1]));
}
#define LDSM4(r0,r1,r2,r3,addr) \
    asm volatile("ldmatrix.sync.aligned.m8n8.x4.shared.b16 {%0,%1,%2,%3}, [%4];" \
        : "=r"(r0),"=r"(r1),"=r"(r2),"=r"(r3) : "r"(addr))
#define CPA(d, s) asm volatile("cp.async.cg.shared.global [%0], [%1], 16;" :: "r"(d), "l"(s))

// ---------------- pure-bf16 split GEMM (mma.sync + cp.async + ldmatrix) ----------------
// C[M,N] = alpha * (A @ B^T) [+bias] [+C],  A = Ah+Al [M,K], B = Bh+Bl [N,K] bf16 planes.
// 3-term split: Ah*Bh + Ah*Bl + Al*Bh, fp32 accum.
// CTA tile 128x64, BK=32, 2-stage cp.async pipeline, 8 warps = 4m x 2n (warp 32x32).
// OUT bits: 1 = write fp32 C, 2 = write split planes Ch/Cl.  ACCM: 0 none, 1 fp32 C, 2 planes.
#define ROWB 80
#define OFF_AL (128*ROWB)
#define OFF_BH (2*128*ROWB)
#define OFF_BL (2*128*ROWB + 64*ROWB)
#define STG_B  (2*128*ROWB + 2*64*ROWB)   // 30720
#define SMEM_DYN (2*STG_B)                // 61440

template<int OUT, int ACCM>
__global__ __launch_bounds__(256, 2) void tgemm(
    const bf16* __restrict__ Ah, const bf16* __restrict__ Al, int lda, long aB, long aH,
    const bf16* __restrict__ Bh, const bf16* __restrict__ Bl, int ldb, long bB, long bH,
    float* __restrict__ C, bf16* __restrict__ Ch, bf16* __restrict__ Cl,
    int ldc, long cB, long cH,
    int K, int nH, float alpha, const float* __restrict__ bias)
{
    extern __shared__ char smraw[];
    uint32_t sbase = s2u(smraw);

    int z = blockIdx.z;
    int bb = z / nH, hh = z - bb * nH;
    long ioff = (long)bb * aB + (long)hh * aH;
    Ah += ioff; Al += ioff;
    ioff = (long)bb * bB + (long)hh * bH;
    Bh += ioff; Bl += ioff;
    long coff = (long)bb * cB + (long)hh * cH;
    if (OUT & 1) C += coff;
    Ch += coff; Cl += coff;    // harmless if unused

    int tid = threadIdx.x, wid = tid >> 5, L = tid & 31;
    int rowBase = blockIdx.y * 128, colBase = blockIdx.x * 64;
    int mwarp = (wid >> 1) * 32, nwarp = (wid & 1) * 32;
    int qrow = L >> 2, qk = L & 3;

    // cp.async source pointers
    int arow = tid >> 1, asel = tid & 1;         // A: rows 0..127, 2x16B each (k half)
    int brow = tid >> 2, bsel = tid & 3;         // B: rows 0..63, 1x16B each
    const bf16* pAh = Ah + (size_t)(rowBase + arow) * lda + asel * 16;
    const bf16* pAl = Al + (size_t)(rowBase + arow) * lda + asel * 16;
    const bf16* pBh = Bh + (size_t)(colBase + brow) * ldb + bsel * 8;
    const bf16* pBl = Bl + (size_t)(colBase + brow) * ldb + bsel * 8;
    uint32_t dA = arow * ROWB + asel * 32;
    uint32_t dB = brow * ROWB + bsel * 16;

    float acc[2][4][4];
#pragma unroll
    for (int mt = 0; mt < 2; mt++)
#pragma unroll
        for (int nt = 0; nt < 4; nt++)
#pragma unroll
            for (int j = 0; j < 4; j++) acc[mt][nt][j] = 0.f;

    const int nC = K / 32;

    auto issue = [&](int c, int stg){
        uint32_t sb = sbase + stg * STG_B;
        const bf16* a0 = pAh + (size_t)c * 32;
        CPA(sb + dA,              a0);
        CPA(sb + dA + 16,         a0 + 8);
        const bf16* a1 = pAl + (size_t)c * 32;
        CPA(sb + OFF_AL + dA,     a1);
        CPA(sb + OFF_AL + dA + 16, a1 + 8);
        CPA(sb + OFF_BH + dB, pBh + (size_t)c * 32);
        CPA(sb + OFF_BL + dB, pBl + (size_t)c * 32);
        asm volatile("cp.async.commit_group;" ::: "memory");
    };

    // ldmatrix per-lane addresses
    uint32_t aoffBase = (uint32_t)(mwarp + (L & 15)) * ROWB + (L >> 4) * 16;
    uint32_t boffBase = (uint32_t)(nwarp + ((L >> 4) * 8 + (L & 7))) * ROWB + ((L >> 3) & 1) * 16;

    issue(0, 0);
#pragma unroll 1
    for (int c = 0; c < nC; c++) {
        if (c + 1 < nC) {
            issue(c + 1, (c + 1) & 1);
            asm volatile("cp.async.wait_group 1;" ::: "memory");
        } else {
            asm volatile("cp.async.wait_group 0;" ::: "memory");
        }
        __syncthreads();

        uint32_t base = sbase + (c & 1) * STG_B;
#pragma unroll
        for (int s = 0; s < 2; s++) {
            uint32_t ah[8], al[8], bh[8], bl[8];
            uint32_t ao = base + aoffBase + s * 32;
            LDSM4(ah[0], ah[1], ah[2], ah[3], ao);
            LDSM4(ah[4], ah[5], ah[6], ah[7], ao + 16 * ROWB);
            LDSM4(al[0], al[1], al[2], al[3], ao + OFF_AL);
            LDSM4(al[4], al[5], al[6], al[7], ao + OFF_AL + 16 * ROWB);
            uint32_t bo = base + OFF_BH + boffBase + s * 32;
            LDSM4(bh[0], bh[1], bh[2], bh[3], bo);
            LDSM4(bh[4], bh[5], bh[6], bh[7], bo + 16 * ROWB);
            LDSM4(bl[0], bl[1], bl[2], bl[3], bo + (OFF_BL - OFF_BH));
            LDSM4(bl[4], bl[5], bl[6], bl[7], bo + (OFF_BL - OFF_BH) + 16 * ROWB);
#pragma unroll
            for (int mt = 0; mt < 2; mt++)
#pragma unroll
                for (int nt = 0; nt < 4; nt++) {
                    mma16816(acc[mt][nt], &ah[mt * 4], &bh[nt * 2]);
                    mma16816(acc[mt][nt], &ah[mt * 4], &bl[nt * 2]);
                    mma16816(acc[mt][nt], &al[mt * 4], &bh[nt * 2]);
                }
        }
        __syncthreads();
    }

    // epilogue
#pragma unroll
    for (int mt = 0; mt < 2; mt++) {
        int row0 = rowBase + mwarp + mt * 16 + qrow;
#pragma unroll
        for (int nt = 0; nt < 4; nt++) {
            int col = colBase + nwarp + nt * 8 + qk * 2;
            float v0 = acc[mt][nt][0] * alpha, v1 = acc[mt][nt][1] * alpha;
            float v2 = acc[mt][nt][2] * alpha, v3 = acc[mt][nt][3] * alpha;
            if (bias) {
                float2 bv = *(const float2*)&bias[col];
                v0 += bv.x; v1 += bv.y; v2 += bv.x; v3 += bv.y;
            }
            size_t o0 = (size_t)row0 * ldc + col;
            size_t o1 = o0 + (size_t)8 * ldc;
            if (ACCM == 1) {
                float2 a0 = *(const float2*)&C[o0];
                float2 a1 = *(const float2*)&C[o1];
                v0 += a0.x; v1 += a0.y; v2 += a1.x; v3 += a1.y;
            }
            if (ACCM == 2) {
                uint32_t h = *(const uint32_t*)&Ch[o0];
                uint32_t l = *(const uint32_t*)&Cl[o0];
                v0 += b2f(h & 0xffff) + b2f(l & 0xffff);
                v1 += b2f(h >> 16)    + b2f(l >> 16);
                h = *(const uint32_t*)&Ch[o1];
                l = *(const uint32_t*)&Cl[o1];
                v2 += b2f(h & 0xffff) + b2f(l & 0xffff);
                v3 += b2f(h >> 16)    + b2f(l >> 16);
            }
            if (OUT & 1) {
                *(float2*)&C[o0] = make_float2(v0, v1);
                *(float2*)&C[o1] = make_float2(v2, v3);
            }
            if (OUT & 2) {
                uint32_t lo, hi;
                hi = packsplit(v0, v1, lo);
                *(uint32_t*)&Ch[o0] = hi; *(uint32_t*)&Cl[o0] = lo;
                hi = packsplit(v2, v3, lo);
                *(uint32_t*)&Ch[o1] = hi; *(uint32_t*)&Cl[o1] = lo;
            }
        }
    }
}

template<int OUT, int ACCM>
static void G(const bf16* Ah, const bf16* Al, int lda, long aB, long aH,
              const bf16* Bh, const bf16* Bl, int ldb, long bB, long bH,
              float* C, bf16* Ch, bf16* Cl, int ldc, long cB, long cH,
              int M, int N, int K, int Z, int nH, float alpha, const float* bias)
{
    dim3 grid(N / 64, M / 128, Z);
    tgemm<OUT, ACCM><<<grid, 256, SMEM_DYN>>>(Ah, Al, lda, aB, aH, Bh, Bl, ldb, bB, bH,
                                              C, Ch, Cl, ldc, cB, cH, K, nH, alpha, bias);
}

// ---------------- weight transpose + split: W fp32 [R,C] -> planes [C,R] ----------------
__global__ void tsplit_k(const float* __restrict__ in, bf16* __restrict__ oh,
                         bf16* __restrict__ ol, int R, int Cc)
{
    __shared__ float t[32][33];
    int c0 = blockIdx.x * 32, r0 = blockIdx.y * 32;
    int x = threadIdx.x, y = threadIdx.y;
#pragma unroll
    for (int j = 0; j < 32; j += 8) t[y + j][x] = in[(size_t)(r0 + y + j) * Cc + c0 + x];
    __syncthreads();
#pragma unroll
    for (int j = 0; j < 32; j += 8)
        splitstore(oh, ol, (size_t)(c0 + y + j) * R + r0 + x, t[x][y + j]);
}

// ---------------- row softmax: fp32 in -> bf16 hi/lo planes out (row length 1024) ----------------
__global__ __launch_bounds__(256) void softmax_k(const float* __restrict__ S,
                                                 bf16* __restrict__ Ph, bf16* __restrict__ Pl)
{
    const float4* row = (const float4*)(S + (size_t)blockIdx.x * 1024);
    int tid = threadIdx.x;
    __shared__ float red[8];

    float4 v = row[tid];
    float m = fmaxf(fmaxf(v.x, v.y), fmaxf(v.z, v.w));
#pragma unroll
    for (int o = 16; o; o >>= 1) m = fmaxf(m, __shfl_xor_sync(0xffffffffu, m, o));
    if ((tid & 31) == 0) red[tid >> 5] = m;
    __syncthreads();
    if (tid < 8) {
        float t = red[tid];
#pragma unroll
        for (int o = 4; o; o >>= 1) t = fmaxf(t, __shfl_xor_sync(0xffu, t, o));
        red[tid] = t;
    }
    __syncthreads();
    m = red[0];

    v.x = __expf(v.x - m); v.y = __expf(v.y - m);
    v.z = __expf(v.z - m); v.w = __expf(v.w - m);
    float s = v.x + v.y + v.z + v.w;
#pragma unroll
    for (int o = 16; o; o >>= 1) s += __shfl_xor_sync(0xffffffffu, s, o);
    __syncthreads();
    if ((tid & 31) == 0) red[tid >> 5] = s;
    __syncthreads();
    if (tid < 8) {
        float t = red[tid];
#pragma unroll
        for (int o = 4; o; o >>= 1) t += __shfl_xor_sync(0xffu, t, o);
        red[tid] = t;
    }
    __syncthreads();
    float inv = 1.f / red[0];
    uint32_t l0, l1;
    uint32_t h0 = packsplit(v.x * inv, v.y * inv, l0);
    uint32_t h1 = packsplit(v.z * inv, v.w * inv, l1);
    size_t idx = (size_t)blockIdx.x * 512 + tid * 2;
    ((uint32_t*)Ph)[idx] = h0; ((uint32_t*)Ph)[idx + 1] = h1;
    ((uint32_t*)Pl)[idx] = l0; ((uint32_t*)Pl)[idx + 1] = l1;
}

// ---------------- out = LayerNorm(t + res)*g + b  (+ optional split planes) ----------------
__global__ void add_ln_k(const float* __restrict__ t, const float* __restrict__ res,
                         const float* __restrict__ g, const float* __restrict__ b,
                         float* __restrict__ out, bf16* __restrict__ oh, bf16* __restrict__ ol)
{
    __shared__ float buf[CH];
    __shared__ float red[256];
    size_t off = (size_t)blockIdx.x * CH;
    int tid = threadIdx.x;
    float s = 0.f;
    for (int i = tid; i < CH; i += 256) { float y = t[off + i] + res[off + i]; buf[i] = y; s += y; }
    red[tid] = s; __syncthreads();
    for (int st = 128; st; st >>= 1) { if (tid < st) red[tid] += red[tid + st]; __syncthreads(); }
    float mean = red[0] * (1.f / CH);
    __syncthreads();
    float v = 0.f;
    for (int i = tid; i < CH; i += 256) { float d = buf[i] - mean; v += d * d; }
    red[tid] = v; __syncthreads();
    for (int st = 128; st; st >>= 1) { if (tid < st) red[tid] += red[tid + st]; __syncthreads(); }
    float rstd = rsqrtf(red[0] * (1.f / CH) + 1e-5f);
    for (int i = tid; i < CH; i += 256) {
        float y = (buf[i] - mean) * rstd * g[i] + b[i];
        out[off + i] = y;
        if (oh) splitstore(oh, ol, off + i, y);
    }
}

// ---------------- input projections ----------------
__global__ void proj_in_k(const float* __restrict__ cx, const float* __restrict__ cy,
                          const float* __restrict__ W, const float* __restrict__ b,
                          float* __restrict__ out, bf16* __restrict__ oh, bf16* __restrict__ ol,
                          int dom)
{
    int idx = blockIdx.x * blockDim.x + threadIdx.x;
    int j = idx & (CH - 1);
    int bn = idx >> 9;
    float x0 = cx[bn];
    const float* y = cy + (size_t)bn * 8 + dom * 2;
    float v = fmaf(x0, W[j], fmaf(y[0], W[CH + j], fmaf(y[1], W[2 * CH + j], b[j])));
    out[idx] = v;
    splitstore(oh, ol, idx, v);
}

__global__ void proj1_k(const float* __restrict__ x, const float* __restrict__ W,
                        const float* __restrict__ b, float* __restrict__ out,
                        bf16* __restrict__ oh, bf16* __restrict__ ol)
{
    int idx = blockIdx.x * blockDim.x + threadIdx.x;
    int j = idx & (CH - 1);
    int i = idx >> 9;
    float v = fmaf(x[i], W[j], b[j]);
    if (out) out[idx] = v;
    splitstore(oh, ol, idx, v);
}

// ---------------- orchestration ----------------
extern "C" void kernel_launch(void* const* d_in, const int* in_sizes, int n_in,
                              void* d_out, int out_size)
{
    const float* cx    = (const float*)d_in[0];
    const float* cy    = (const float*)d_in[1];
    const float* txp   = (const float*)d_in[2];
    const float* in_W  = (const float*)d_in[3];
    const float* in_b  = (const float*)d_in[4];
    const float* cx_W  = (const float*)d_in[5];
    const float* cx_b  = (const float*)d_in[6];
    const float* tx_W  = (const float*)d_in[7];
    const float* tx_b  = (const float*)d_in[8];
    const float* sc_Wk = (const float*)d_in[9];
    const float* sc_Wv = (const float*)d_in[10];
    const float* sc_Wq = (const float*)d_in[11];
    const float* sc_Wf = (const float*)d_in[12];
    const float* sc_bf = (const float*)d_in[13];
    const float* sc_g  = (const float*)d_in[14];
    const float* sc_b  = (const float*)d_in[15];
    const float* ca_Wk = (const float*)d_in[16];
    const float* ca_Wv = (const float*)d_in[17];
    const float* ca_Wq = (const float*)d_in[18];
    const float* ca_Wf = (const float*)d_in[19];
    const float* ca_bf = (const float*)d_in[20];
    const float* ca_g  = (const float*)d_in[21];
    const float* ca_b  = (const float*)d_in[22];

    cudaFuncSetAttribute(tgemm<1,0>, cudaFuncAttributeMaxDynamicSharedMemorySize, SMEM_DYN);
    cudaFuncSetAttribute(tgemm<1,1>, cudaFuncAttributeMaxDynamicSharedMemorySize, SMEM_DYN);
    cudaFuncSetAttribute(tgemm<2,0>, cudaFuncAttributeMaxDynamicSharedMemorySize, SMEM_DYN);
    cudaFuncSetAttribute(tgemm<2,2>, cudaFuncAttributeMaxDynamicSharedMemorySize, SMEM_DYN);

    void* p;
    cudaGetSymbolAddress(&p, g_e);   float* e   = (float*)p;
    cudaGetSymbolAddress(&p, g_e1);  float* e1b = (float*)p;
    cudaGetSymbolAddress(&p, g_e2);  float* e2b = (float*)p;
    cudaGetSymbolAddress(&p, g_e3);  float* e3b = (float*)p;
    cudaGetSymbolAddress(&p, g_S);   float* Sb  = (float*)p;
    cudaGetSymbolAddress(&p, g_t);   float* tb  = (float*)p;
    cudaGetSymbolAddress(&p, g_q);   float* qb  = (float*)p;
    cudaGetSymbolAddress(&p, g_eh);  bf16* eh  = (bf16*)p;  cudaGetSymbolAddress(&p, g_el);  bf16* el  = (bf16*)p;
    cudaGetSymbolAddress(&p, g_e1h); bf16* e1h = (bf16*)p;  cudaGetSymbolAddress(&p, g_e1l); bf16* e1l = (bf16*)p;
    cudaGetSymbolAddress(&p, g_e2h); bf16* e2h = (bf16*)p;  cudaGetSymbolAddress(&p, g_e2l); bf16* e2l = (bf16*)p;
    cudaGetSymbolAddress(&p, g_e3h); bf16* e3h = (bf16*)p;  cudaGetSymbolAddress(&p, g_e3l); bf16* e3l = (bf16*)p;
    cudaGetSymbolAddress(&p, g_Kh);  bf16* Kh  = (bf16*)p;  cudaGetSymbolAddress(&p, g_Kl);  bf16* Kl  = (bf16*)p;
    cudaGetSymbolAddress(&p, g_Qh);  bf16* Qh  = (bf16*)p;  cudaGetSymbolAddress(&p, g_Ql);  bf16* Ql  = (bf16*)p;
    cudaGetSymbolAddress(&p, g_K2h); bf16* K2h = (bf16*)p;  cudaGetSymbolAddress(&p, g_K2l); bf16* K2l = (bf16*)p;
    cudaGetSymbolAddress(&p, g_Q2h); bf16* Q2h = (bf16*)p;  cudaGetSymbolAddress(&p, g_Q2l); bf16* Q2l = (bf16*)p;
    cudaGetSymbolAddress(&p, g_Vth); bf16* Vth = (bf16*)p;  cudaGetSymbolAddress(&p, g_Vtl); bf16* Vtl = (bf16*)p;
    cudaGetSymbolAddress(&p, g_Vt2h);bf16* Vt2h= (bf16*)p;  cudaGetSymbolAddress(&p, g_Vt2l);bf16* Vt2l= (bf16*)p;
    cudaGetSymbolAddress(&p, g_rh);  bf16* rh  = (bf16*)p;  cudaGetSymbolAddress(&p, g_rl);  bf16* rl  = (bf16*)p;
    cudaGetSymbolAddress(&p, g_qh);  bf16* qh  = (bf16*)p;  cudaGetSymbolAddress(&p, g_ql);  bf16* ql  = (bf16*)p;
    cudaGetSymbolAddress(&p, g_k0h); bf16* k0h = (bf16*)p;  cudaGetSymbolAddress(&p, g_k0l); bf16* k0l = (bf16*)p;
    cudaGetSymbolAddress(&p, g_Sh);  bf16* Sh  = (bf16*)p;  cudaGetSymbolAddress(&p, g_Sl);  bf16* Sl  = (bf16*)p;
    cudaGetSymbolAddress(&p, g_Wth); bf16* Wth = (bf16*)p;  cudaGetSymbolAddress(&p, g_Wtl); bf16* Wtl = (bf16*)p;

    const int totE = TOK * CH;

    // ---- transpose+split all weights once ----
    const long WSET = 1310720;
    auto wsH = [&](int grp, int i, int w) -> bf16* {
        bf16* base = Wth + (grp * 2 + i) * WSET;
        return (w < 3) ? base + (long)w * 262144 : base + 786432;
    };
    auto wsL = [&](int grp, int i, int w) -> bf16* {
        bf16* base = Wtl + (grp * 2 + i) * WSET;
        return (w < 3) ? base + (long)w * 262144 : base + 786432;
    };
    {
        dim3 tb32(32, 8);
        for (int i = 0; i < 2; i++) {
            tsplit_k<<<dim3(16, 16), tb32>>>(sc_Wk + (size_t)i * 262144, wsH(0,i,0), wsL(0,i,0), 512, 512);
            tsplit_k<<<dim3(16, 16), tb32>>>(sc_Wv + (size_t)i * 262144, wsH(0,i,1), wsL(0,i,1), 512, 512);
            tsplit_k<<<dim3(16, 16), tb32>>>(sc_Wq + (size_t)i * 262144, wsH(0,i,2), wsL(0,i,2), 512, 512);
            tsplit_k<<<dim3(16, 32), tb32>>>(sc_Wf + (size_t)i * 524288, wsH(0,i,3), wsL(0,i,3), 1024, 512);
            tsplit_k<<<dim3(16, 16), tb32>>>(ca_Wk + (size_t)i * 262144, wsH(1,i,0), wsL(1,i,0), 512, 512);
            tsplit_k<<<dim3(16, 16), tb32>>>(ca_Wv + (size_t)i * 262144, wsH(1,i,1), wsL(1,i,1), 512, 512);
            tsplit_k<<<dim3(16, 16), tb32>>>(ca_Wq + (size_t)i * 262144, wsH(1,i,2), wsL(1,i,2), 512, 512);
            tsplit_k<<<dim3(16, 32), tb32>>>(ca_Wf + (size_t)i * 524288, wsH(1,i,3), wsL(1,i,3), 1024, 512);
        }
    }

    proj_in_k<<<totE / 256, 256>>>(cx, cy, in_W, in_b, e,   eh,  el,  0);
    proj_in_k<<<totE / 256, 256>>>(cx, cy, in_W, in_b, e1b, e1h, e1l, 1);
    proj_in_k<<<totE / 256, 256>>>(cx, cy, in_W, in_b, e2b, e2h, e2l, 2);
    proj_in_k<<<totE / 256, 256>>>(cx, cy, in_W, in_b, e3b, e3h, e3l, 3);
    proj1_k<<<(CB * CM * CH) / 256, 256>>>(txp, tx_W, tx_b, qb, qh, ql);
    proj1_k<<<totE / 256, 256>>>(cx, cx_W, cx_b, nullptr, k0h, k0l);

    auto sc_layer = [&](const bf16* x2h, const bf16* x2l, bool self, int i) {
        const bf16 *WkTh = wsH(0,i,0), *WkTl = wsL(0,i,0);
        const bf16 *WvTh = wsH(0,i,1), *WvTl = wsL(0,i,1);
        const bf16 *WqTh = wsH(0,i,2), *WqTl = wsL(0,i,2);
        const bf16 *WfTh = wsH(0,i,3), *WfTl = wsL(0,i,3);
        const float* bfp = sc_bf + (size_t)i * CH;
        const float* lg  = sc_g  + (size_t)i * CH;
        const float* lb  = sc_b  + (size_t)i * CH;
        G<2,0>(eh, el, CH,0,0, WkTh,WkTl, CH,0,0, nullptr, Kh, Kl, CH,0,0, TOK, CH, CH, 1,1, 1.f, nullptr);
        G<2,0>(eh, el, CH,0,0, WqTh,WqTl, CH,0,0, nullptr, Qh, Ql, CH,0,0, TOK, CH, CH, 1,1, 1.f, nullptr);
        // Vt = Wv^T @ e^T : [CH, TOK]
        G<2,0>(WvTh,WvTl, CH,0,0, eh,el, CH,0,0, nullptr, Vth,Vtl, TOK,0,0, CH, TOK, CH, 1,1, 1.f, nullptr);
        if (!self) {
            G<2,0>(x2h,x2l, CH,0,0, WkTh,WkTl, CH,0,0, nullptr, K2h,K2l, CH,0,0, TOK, CH, CH, 1,1, 1.f, nullptr);
            G<2,0>(x2h,x2l, CH,0,0, WqTh,WqTl, CH,0,0, nullptr, Q2h,Q2l, CH,0,0, TOK, CH, CH, 1,1, 1.f, nullptr);
            G<2,0>(WvTh,WvTl, CH,0,0, x2h,x2l, CH,0,0, nullptr, Vt2h,Vt2l, TOK,0,0, CH, TOK, CH, 1,1, 1.f, nullptr);
        }
        const int d = 256, h = 2, Z = CB * h;
        const bf16* Qsh[4] = {Qh, Q2h, Q2h, Qh};  const bf16* Qsl[4] = {Ql, Q2l, Q2l, Ql};
        const bf16* Ksh[4] = {Kh, K2h, Kh, K2h};  const bf16* Ksl[4] = {Kl, K2l, Kl, K2l};
        const bf16* Vsh[4] = {Vth, Vt2h, Vth, Vt2h};
        const bf16* Vsl[4] = {Vtl, Vt2l, Vtl, Vt2l};
        int nT = self ? 1 : 4;
        for (int t = 0; t < nT; t++) {
            G<1,0>(Qsh[t],Qsl[t], CH, (long)CN*CH, d, Ksh[t],Ksl[t], CH, (long)CN*CH, d,
                   Sb, nullptr, nullptr, CN, (long)h*CN*CN, (long)CN*CN,
                   CN, CN, d, Z, h, 0.0625f, nullptr);              // 1/sqrt(256)
            softmax_k<<<Z * CN, 256>>>(Sb, Sh, Sl);
            float ao = self ? 4.f : 1.f;
            if (t == 0)
                G<2,0>(Sh,Sl, CN, (long)h*CN*CN, (long)CN*CN, Vsh[t],Vsl[t], TOK, CN, (long)d*TOK,
                       nullptr, rh, rl, CH, (long)CN*CH, d, CN, d, CN, Z, h, ao, nullptr);
            else
                G<2,2>(Sh,Sl, CN, (long)h*CN*CN, (long)CN*CN, Vsh[t],Vsl[t], TOK, CN, (long)d*TOK,
                       nullptr, rh, rl, CH, (long)CN*CH, d, CN, d, CN, Z, h, 1.f, nullptr);
        }
        // tb = e@Wf_top + bf ; tb += r@Wf_bot
        G<1,0>(eh,el, CH,0,0, WfTh,WfTl, 1024,0,0, tb, nullptr,nullptr, CH,0,0, TOK, CH, CH, 1,1, 1.f, bfp);
        G<1,1>(rh,rl, CH,0,0, WfTh+512,WfTl+512, 1024,0,0, tb, nullptr,nullptr, CH,0,0, TOK, CH, CH, 1,1, 1.f, nullptr);
        add_ln_k<<<TOK, 256>>>(tb, e, lg, lb, e, eh, el);
    };

    sc_layer(eh,  el,  true,  0); sc_layer(eh,  el,  true,  1);
    sc_layer(e1h, e1l, false, 0); sc_layer(e1h, e1l, false, 1);
    sc_layer(e2h, e2l, false, 0); sc_layer(e2h, e2l, false, 1);
    sc_layer(e3h, e3l, false, 0); sc_layer(e3h, e3l, false, 1);

    // cross attention: q = _attn(k0, e, q) twice, h=4, d=128
    for (int i = 0; i < 2; i++) {
        const bf16 *WkTh = wsH(1,i,0), *WkTl = wsL(1,i,0);
        const bf16 *WvTh = wsH(1,i,1), *WvTl = wsL(1,i,1);
        const bf16 *WqTh = wsH(1,i,2), *WqTl = wsL(1,i,2);
        const bf16 *WfTh = wsH(1,i,3), *WfTl = wsL(1,i,3);
        const float* bfp = ca_bf + (size_t)i * CH;
        const float* lg  = ca_g  + (size_t)i * CH;
        const float* lb  = ca_b  + (size_t)i * CH;
        G<2,0>(k0h,k0l, CH,0,0, WkTh,WkTl, CH,0,0, nullptr, Kh,Kl, CH,0,0, TOK, CH, CH, 1,1, 1.f, nullptr);
        G<2,0>(WvTh,WvTl, CH,0,0, eh,el, CH,0,0, nullptr, Vth,Vtl, TOK,0,0, CH, TOK, CH, 1,1, 1.f, nullptr);
        G<2,0>(qh,ql, CH,0,0, WqTh,WqTl, CH,0,0, nullptr, Qh,Ql, CH,0,0, TOK, CH, CH, 1,1, 1.f, nullptr);
        const int d = 128, h = 4, Z = CB * h;
        G<1,0>(Qh,Ql, CH, (long)CM*CH, d, Kh,Kl, CH, (long)CN*CH, d,
               Sb, nullptr, nullptr, CN, (long)h*CM*CN, (long)CM*CN,
               CM, CN, d, Z, h, 0.0883883476483184f, nullptr);      // 1/sqrt(128)
        softmax_k<<<Z * CM, 256>>>(Sb, Sh, Sl);
        G<2,0>(Sh,Sl, CN, (long)h*CM*CN, (long)CM*CN, Vth,Vtl, TOK, CN, (long)d*TOK,
               nullptr, rh, rl, CH, (long)CM*CH, d, CM, d, CN, Z, h, 1.f, nullptr);
        G<1,0>(qh,ql, CH,0,0, WfTh,WfTl, 1024,0,0, tb, nullptr,nullptr, CH,0,0, CB*CM, CH, CH, 1,1, 1.f, bfp);
        G<1,1>(rh,rl, CH,0,0, WfTh+512,WfTl+512, 1024,0,0, tb, nullptr,nullptr, CH,0,0, CB*CM, CH, CH, 1,1, 1.f, nullptr);
        if (i == 1)
            add_ln_k<<<CB * CM, 256>>>(tb, qb, lg, lb, (float*)d_out, nullptr, nullptr);
        else
            add_ln_k<<<CB * CM, 256>>>(tb, qb, lg, lb, qb, qh, ql);
    }
}

// round 15
// speedup vs baseline: 3.0674x; 1.1572x over previous
#include <cuda_runtime.h>
#include <cuda_bf16.h>
#include <math.h>
#include <stdint.h>
#include <string.h>

#define CB 4
#define CN 1024
#define CM 1024
#define CH 512
#define TOK (CB*CN)
#define TE (TOK*CH)

typedef __nv_bfloat16 bf16;

// ---------------- scratch (device globals; no allocation allowed) ----------------
__device__ __align__(16) float g_e [TE];
__device__ __align__(16) float g_t [TE];
__device__ __align__(16) float g_q [TE];
__device__ __align__(16) float g_S [32u*1024u*1024u];                    // up to 4 terms x 8 z
__device__ __align__(16) bf16 g_Sh[32u*1024u*1024u], g_Sl[32u*1024u*1024u];
__device__ __align__(16) bf16 g_erh [TOK*1024], g_erl [TOK*1024];        // [e | r]
__device__ __align__(16) bf16 g_er2h[TOK*1024], g_er2l[TOK*1024];        // [q | r] (cross)
__device__ __align__(16) bf16 g_KQh[2*TOK*1024], g_KQl[2*TOK*1024];      // [K|Q], [K2|Q2]
__device__ __align__(16) bf16 g_Vth[2*TE], g_Vtl[2*TE];                  // Vt, Vt2
__device__ __align__(16) bf16 g_r4h[4*TE], g_r4l[4*TE];
__device__ __align__(16) bf16 g_e1h[TE], g_e1l[TE];
__device__ __align__(16) bf16 g_e2h[TE], g_e2l[TE];
__device__ __align__(16) bf16 g_e3h[TE], g_e3l[TE];
__device__ __align__(16) bf16 g_k0h[TE], g_k0l[TE];
__device__ __align__(16) bf16 g_Wth[4*1310720], g_Wtl[4*1310720];

// ---------------- helpers ----------------
static __device__ __forceinline__ uint32_t s2u(const void* p){
    uint32_t a;
    asm("{ .reg .u64 t; cvta.to.shared.u64 t, %1; cvt.u32.u64 %0, t; }" : "=r"(a) : "l"(p));
    return a;
}
static __device__ __forceinline__ unsigned short bfbits(bf16 h){
    return reinterpret_cast<unsigned short&>(h);
}
static __device__ __forceinline__ float b2f(uint32_t bits){
    return __uint_as_float(bits << 16);
}
static __device__ __forceinline__ uint32_t packsplit(float a, float b, uint32_t& lo){
    bf16 ha = __float2bfloat16(a), hb = __float2bfloat16(b);
    bf16 la = __float2bfloat16(a - b2f(bfbits(ha)));
    bf16 lb = __float2bfloat16(b - b2f(bfbits(hb)));
    lo = (uint32_t)bfbits(la) | ((uint32_t)bfbits(lb) << 16);
    return (uint32_t)bfbits(ha) | ((uint32_t)bfbits(hb) << 16);
}
static __device__ __forceinline__ void splitstore(bf16* oh, bf16* ol, size_t idx, float v){
    bf16 h = __float2bfloat16(v);
    oh[idx] = h;
    ol[idx] = __float2bfloat16(v - b2f(bfbits(h)));
}
static __device__ __forceinline__ void mma16816(float* c, const uint32_t* a, const uint32_t* b){
    asm volatile(
        "mma.sync.aligned.m16n8k16.row.col.f32.bf16.bf16.f32 "
        "{%0,%1,%2,%3}, {%4,%5,%6,%7}, {%8,%9}, {%0,%1,%2,%3};"
        : "+f"(c[0]), "+f"(c[1]), "+f"(c[2]), "+f"(c[3])
        : "r"(a[0]), "r"(a[1]), "r"(a[2]), "r"(a[3]), "r"(b[0]), "r"(b[1]));
}
#define LDSM4(r0,r1,r2,r3,addr) \
    asm volatile("ldmatrix.sync.aligned.m8n8.x4.shared.b16 {%0,%1,%2,%3}, [%4];" \
        : "=r"(r0),"=r"(r1),"=r"(r2),"=r"(r3) : "r"(addr))
#define CPA(d, s) asm volatile("cp.async.cg.shared.global [%0], [%1], 16;" :: "r"(d), "l"(s))

// per-term offset tables for batched multi-term GEMMs
struct Tabs { long a[4]; long b[4]; long c[4]; int nPerT; };

// ---------------- pure-bf16 split GEMM ----------------
// C[M,N] = alpha * (A @ B^T) [+bias],  A = Ah+Al [M,K], B = Bh+Bl [N,K] planes.
// 3-term: Ah*Bh + Ah*Bl + Al*Bh, fp32 accum. CTA 128x64, BK=32, 2-stage cp.async.
// OUT: 1 = fp32 C, 2 = split planes Ch/Cl.
#define ROWB 80
#define OFF_AL (128*ROWB)
#define OFF_BH (2*128*ROWB)
#define OFF_BL (2*128*ROWB + 64*ROWB)
#define STG_B  (2*128*ROWB + 2*64*ROWB)
#define SMEM_DYN (2*STG_B)

template<int OUT>
__global__ __launch_bounds__(256, 2) void tgemm(
    const bf16* __restrict__ Ah, const bf16* __restrict__ Al, int lda, long aB, long aH,
    const bf16* __restrict__ Bh, const bf16* __restrict__ Bl, int ldb, long bB, long bH,
    float* __restrict__ C, bf16* __restrict__ Ch, bf16* __restrict__ Cl,
    int ldc, long cB, long cH,
    int K, int nH, float alpha, const float* __restrict__ bias, Tabs tab)
{
    extern __shared__ char smraw[];
    uint32_t sbase = s2u(smraw);

    int z = blockIdx.z;
    int t = z / tab.nPerT; int rz = z - t * tab.nPerT;
    int bb = rz / nH, hh = rz - bb * nH;
    long off = tab.a[t] + (long)bb * aB + (long)hh * aH;
    Ah += off; Al += off;
    off = tab.b[t] + (long)bb * bB + (long)hh * bH;
    Bh += off; Bl += off;
    off = tab.c[t] + (long)bb * cB + (long)hh * cH;
    if (OUT & 1) C += off;
    if (OUT & 2) { Ch += off; Cl += off; }

    int tid = threadIdx.x, wid = tid >> 5, L = tid & 31;
    int rowBase = blockIdx.y * 128, colBase = blockIdx.x * 64;
    int mwarp = (wid >> 1) * 32, nwarp = (wid & 1) * 32;
    int qrow = L >> 2, qk = L & 3;

    int arow = tid >> 1, asel = tid & 1;
    int brow = tid >> 2, bsel = tid & 3;
    const bf16* pAh = Ah + (size_t)(rowBase + arow) * lda + asel * 16;
    const bf16* pAl = Al + (size_t)(rowBase + arow) * lda + asel * 16;
    const bf16* pBh = Bh + (size_t)(colBase + brow) * ldb + bsel * 8;
    const bf16* pBl = Bl + (size_t)(colBase + brow) * ldb + bsel * 8;
    uint32_t dA = arow * ROWB + asel * 32;
    uint32_t dB = brow * ROWB + bsel * 16;

    float acc[2][4][4];
#pragma unroll
    for (int mt = 0; mt < 2; mt++)
#pragma unroll
        for (int nt = 0; nt < 4; nt++)
#pragma unroll
            for (int j = 0; j < 4; j++) acc[mt][nt][j] = 0.f;

    const int nC = K / 32;

    auto issue = [&](int c, int stg){
        uint32_t sb = sbase + stg * STG_B;
        const bf16* a0 = pAh + (size_t)c * 32;
        CPA(sb + dA,               a0);
        CPA(sb + dA + 16,          a0 + 8);
        const bf16* a1 = pAl + (size_t)c * 32;
        CPA(sb + OFF_AL + dA,      a1);
        CPA(sb + OFF_AL + dA + 16, a1 + 8);
        CPA(sb + OFF_BH + dB, pBh + (size_t)c * 32);
        CPA(sb + OFF_BL + dB, pBl + (size_t)c * 32);
        asm volatile("cp.async.commit_group;" ::: "memory");
    };

    uint32_t aoffBase = (uint32_t)(mwarp + (L & 15)) * ROWB + (L >> 4) * 16;
    uint32_t boffBase = (uint32_t)(nwarp + ((L >> 4) * 8 + (L & 7))) * ROWB + ((L >> 3) & 1) * 16;

    issue(0, 0);
#pragma unroll 1
    for (int c = 0; c < nC; c++) {
        if (c + 1 < nC) {
            issue(c + 1, (c + 1) & 1);
            asm volatile("cp.async.wait_group 1;" ::: "memory");
        } else {
            asm volatile("cp.async.wait_group 0;" ::: "memory");
        }
        __syncthreads();

        uint32_t base = sbase + (c & 1) * STG_B;
#pragma unroll
        for (int s = 0; s < 2; s++) {
            uint32_t ah[8], al[8], bh[8], bl[8];
            uint32_t ao = base + aoffBase + s * 32;
            LDSM4(ah[0], ah[1], ah[2], ah[3], ao);
            LDSM4(ah[4], ah[5], ah[6], ah[7], ao + 16 * ROWB);
            LDSM4(al[0], al[1], al[2], al[3], ao + OFF_AL);
            LDSM4(al[4], al[5], al[6], al[7], ao + OFF_AL + 16 * ROWB);
            uint32_t bo = base + OFF_BH + boffBase + s * 32;
            LDSM4(bh[0], bh[1], bh[2], bh[3], bo);
            LDSM4(bh[4], bh[5], bh[6], bh[7], bo + 16 * ROWB);
            LDSM4(bl[0], bl[1], bl[2], bl[3], bo + (OFF_BL - OFF_BH));
            LDSM4(bl[4], bl[5], bl[6], bl[7], bo + (OFF_BL - OFF_BH) + 16 * ROWB);
#pragma unroll
            for (int mt = 0; mt < 2; mt++)
#pragma unroll
                for (int nt = 0; nt < 4; nt++) {
                    mma16816(acc[mt][nt], &ah[mt * 4], &bh[nt * 2]);
                    mma16816(acc[mt][nt], &ah[mt * 4], &bl[nt * 2]);
                    mma16816(acc[mt][nt], &al[mt * 4], &bh[nt * 2]);
                }
        }
        __syncthreads();
    }

#pragma unroll
    for (int mt = 0; mt < 2; mt++) {
        int row0 = rowBase + mwarp + mt * 16 + qrow;
#pragma unroll
        for (int nt = 0; nt < 4; nt++) {
            int col = colBase + nwarp + nt * 8 + qk * 2;
            float v0 = acc[mt][nt][0] * alpha, v1 = acc[mt][nt][1] * alpha;
            float v2 = acc[mt][nt][2] * alpha, v3 = acc[mt][nt][3] * alpha;
            if (bias) {
                float2 bv = *(const float2*)&bias[col];
                v0 += bv.x; v1 += bv.y; v2 += bv.x; v3 += bv.y;
            }
            size_t o0 = (size_t)row0 * ldc + col;
            size_t o1 = o0 + (size_t)8 * ldc;
            if (OUT & 1) {
                *(float2*)&C[o0] = make_float2(v0, v1);
                *(float2*)&C[o1] = make_float2(v2, v3);
            }
            if (OUT & 2) {
                uint32_t lo, hi;
                hi = packsplit(v0, v1, lo);
                *(uint32_t*)&Ch[o0] = hi; *(uint32_t*)&Cl[o0] = lo;
                hi = packsplit(v2, v3, lo);
                *(uint32_t*)&Ch[o1] = hi; *(uint32_t*)&Cl[o1] = lo;
            }
        }
    }
}

template<int OUT>
static void G(const bf16* Ah, const bf16* Al, int lda, long aB, long aH,
              const bf16* Bh, const bf16* Bl, int ldb, long bB, long bH,
              float* C, bf16* Ch, bf16* Cl, int ldc, long cB, long cH,
              int M, int N, int K, int Z, int nH, float alpha, const float* bias,
              const Tabs* tabs = nullptr)
{
    Tabs tt;
    if (tabs) tt = *tabs;
    else { memset(&tt, 0, sizeof(tt)); tt.nPerT = Z; }
    dim3 grid(N / 64, M / 128, Z);
    tgemm<OUT><<<grid, 256, SMEM_DYN>>>(Ah, Al, lda, aB, aH, Bh, Bl, ldb, bB, bH,
                                        C, Ch, Cl, ldc, cB, cH, K, nH, alpha, bias, tt);
}

// ---------------- batched weight transpose+split ----------------
struct TSE { const float* s; bf16* h; bf16* l; };
struct TS12 { TSE e[12]; };
struct TS4  { TSE e[4]; };

template<int R>
static __device__ __forceinline__ void tsplit_body(const float* in, bf16* oh, bf16* ol)
{
    __shared__ float t[32][33];
    const int Cc = 512;
    int c0 = blockIdx.x * 32, r0 = blockIdx.y * 32;
    int x = threadIdx.x, y = threadIdx.y;
#pragma unroll
    for (int j = 0; j < 32; j += 8) t[y + j][x] = in[(size_t)(r0 + y + j) * Cc + c0 + x];
    __syncthreads();
#pragma unroll
    for (int j = 0; j < 32; j += 8)
        splitstore(oh, ol, (size_t)(c0 + y + j) * R + r0 + x, t[x][y + j]);
}
__global__ void tsplit12_k(TS12 p){ TSE w = p.e[blockIdx.z]; tsplit_body<512>(w.s, w.h, w.l); }
__global__ void tsplit4_k (TS4  p){ TSE w = p.e[blockIdx.z]; tsplit_body<1024>(w.s, w.h, w.l); }

// ---------------- row softmax: fp32 in -> bf16 planes (row length 1024) ----------------
__global__ __launch_bounds__(256) void softmax_k(const float* __restrict__ S,
                                                 bf16* __restrict__ Ph, bf16* __restrict__ Pl,
                                                 float oscale)
{
    const float4* row = (const float4*)(S + (size_t)blockIdx.x * 1024);
    int tid = threadIdx.x;
    __shared__ float red[8];

    float4 v = row[tid];
    float m = fmaxf(fmaxf(v.x, v.y), fmaxf(v.z, v.w));
#pragma unroll
    for (int o = 16; o; o >>= 1) m = fmaxf(m, __shfl_xor_sync(0xffffffffu, m, o));
    if ((tid & 31) == 0) red[tid >> 5] = m;
    __syncthreads();
    if (tid < 8) {
        float t = red[tid];
#pragma unroll
        for (int o = 4; o; o >>= 1) t = fmaxf(t, __shfl_xor_sync(0xffu, t, o));
        red[tid] = t;
    }
    __syncthreads();
    m = red[0];

    v.x = __expf(v.x - m); v.y = __expf(v.y - m);
    v.z = __expf(v.z - m); v.w = __expf(v.w - m);
    float s = v.x + v.y + v.z + v.w;
#pragma unroll
    for (int o = 16; o; o >>= 1) s += __shfl_xor_sync(0xffffffffu, s, o);
    __syncthreads();
    if ((tid & 31) == 0) red[tid >> 5] = s;
    __syncthreads();
    if (tid < 8) {
        float t = red[tid];
#pragma unroll
        for (int o = 4; o; o >>= 1) t += __shfl_xor_sync(0xffu, t, o);
        red[tid] = t;
    }
    __syncthreads();
    float inv = oscale / red[0];
    uint32_t l0, l1;
    uint32_t h0 = packsplit(v.x * inv, v.y * inv, l0);
    uint32_t h1 = packsplit(v.z * inv, v.w * inv, l1);
    size_t idx = (size_t)blockIdx.x * 512 + tid * 2;
    ((uint32_t*)Ph)[idx] = h0; ((uint32_t*)Ph)[idx + 1] = h1;
    ((uint32_t*)Pl)[idx] = l0; ((uint32_t*)Pl)[idx + 1] = l1;
}

// ---------------- 4-term reduce: er[:,512:] = sum_t r4[t] ----------------
__global__ void rsum_k(const bf16* __restrict__ h4, const bf16* __restrict__ l4,
                       bf16* __restrict__ oh, bf16* __restrict__ ol)
{
    int i2 = blockIdx.x * blockDim.x + threadIdx.x;
    int base = i2 * 2;
    int row = base >> 9, col = base & 511;
    float v0 = 0.f, v1 = 0.f;
#pragma unroll
    for (int t = 0; t < 4; t++) {
        uint32_t h = *(const uint32_t*)&h4[(size_t)t * TE + base];
        uint32_t l = *(const uint32_t*)&l4[(size_t)t * TE + base];
        v0 += b2f((h & 0xffff)) + b2f((l & 0xffff));
        v1 += b2f((h >> 16))    + b2f((l >> 16));
    }
    size_t o = (size_t)row * 1024 + 512 + col;
    uint32_t lo, hi = packsplit(v0, v1, lo);
    *(uint32_t*)&oh[o] = hi;
    *(uint32_t*)&ol[o] = lo;
}

// ---------------- out = LayerNorm(t + res)*g + b  (+ planes at plane-ld) ----------------
__global__ void add_ln_k(const float* __restrict__ t, const float* __restrict__ res,
                         const float* __restrict__ g, const float* __restrict__ b,
                         float* __restrict__ out, bf16* __restrict__ oh, bf16* __restrict__ ol,
                         int pld)
{
    __shared__ float buf[CH];
    __shared__ float red[256];
    size_t off = (size_t)blockIdx.x * CH;
    int tid = threadIdx.x;
    float s = 0.f;
    for (int i = tid; i < CH; i += 256) { float y = t[off + i] + res[off + i]; buf[i] = y; s += y; }
    red[tid] = s; __syncthreads();
    for (int st = 128; st; st >>= 1) { if (tid < st) red[tid] += red[tid + st]; __syncthreads(); }
    float mean = red[0] * (1.f / CH);
    __syncthreads();
    float v = 0.f;
    for (int i = tid; i < CH; i += 256) { float d = buf[i] - mean; v += d * d; }
    red[tid] = v; __syncthreads();
    for (int st = 128; st; st >>= 1) { if (tid < st) red[tid] += red[tid + st]; __syncthreads(); }
    float rstd = rsqrtf(red[0] * (1.f / CH) + 1e-5f);
    size_t poff = (size_t)blockIdx.x * pld;
    for (int i = tid; i < CH; i += 256) {
        float y = (buf[i] - mean) * rstd * g[i] + b[i];
        out[off + i] = y;
        if (oh) splitstore(oh, ol, poff + i, y);
    }
}

// ---------------- input projections ----------------
__global__ void proj_in_k(const float* __restrict__ cx, const float* __restrict__ cy,
                          const float* __restrict__ W, const float* __restrict__ b,
                          float* __restrict__ out, bf16* __restrict__ oh, bf16* __restrict__ ol,
                          int pld, int dom)
{
    int idx = blockIdx.x * blockDim.x + threadIdx.x;
    int j = idx & (CH - 1);
    int bn = idx >> 9;
    float x0 = cx[bn];
    const float* y = cy + (size_t)bn * 8 + dom * 2;
    float v = fmaf(x0, W[j], fmaf(y[0], W[CH + j], fmaf(y[1], W[2 * CH + j], b[j])));
    if (out) out[idx] = v;
    splitstore(oh, ol, (size_t)bn * pld + j, v);
}

__global__ void proj1_k(const float* __restrict__ x, const float* __restrict__ W,
                        const float* __restrict__ b, float* __restrict__ out,
                        bf16* __restrict__ oh, bf16* __restrict__ ol, int pld)
{
    int idx = blockIdx.x * blockDim.x + threadIdx.x;
    int j = idx & (CH - 1);
    int i = idx >> 9;
    float v = fmaf(x[i], W[j], b[j]);
    if (out) out[idx] = v;
    splitstore(oh, ol, (size_t)i * pld + j, v);
}

// ---------------- orchestration ----------------
extern "C" void kernel_launch(void* const* d_in, const int* in_sizes, int n_in,
                              void* d_out, int out_size)
{
    const float* cx    = (const float*)d_in[0];
    const float* cy    = (const float*)d_in[1];
    const float* txp   = (const float*)d_in[2];
    const float* in_W  = (const float*)d_in[3];
    const float* in_b  = (const float*)d_in[4];
    const float* cx_W  = (const float*)d_in[5];
    const float* cx_b  = (const float*)d_in[6];
    const float* tx_W  = (const float*)d_in[7];
    const float* tx_b  = (const float*)d_in[8];
    const float* sc_Wk = (const float*)d_in[9];
    const float* sc_Wv = (const float*)d_in[10];
    const float* sc_Wq = (const float*)d_in[11];
    const float* sc_Wf = (const float*)d_in[12];
    const float* sc_bf = (const float*)d_in[13];
    const float* sc_g  = (const float*)d_in[14];
    const float* sc_b  = (const float*)d_in[15];
    const float* ca_Wk = (const float*)d_in[16];
    const float* ca_Wv = (const float*)d_in[17];
    const float* ca_Wq = (const float*)d_in[18];
    const float* ca_Wf = (const float*)d_in[19];
    const float* ca_bf = (const float*)d_in[20];
    const float* ca_g  = (const float*)d_in[21];
    const float* ca_b  = (const float*)d_in[22];

    cudaFuncSetAttribute(tgemm<1>, cudaFuncAttributeMaxDynamicSharedMemorySize, SMEM_DYN);
    cudaFuncSetAttribute(tgemm<2>, cudaFuncAttributeMaxDynamicSharedMemorySize, SMEM_DYN);

    void* p;
    cudaGetSymbolAddress(&p, g_e);    float* e    = (float*)p;
    cudaGetSymbolAddress(&p, g_t);    float* tb   = (float*)p;
    cudaGetSymbolAddress(&p, g_q);    float* qb   = (float*)p;
    cudaGetSymbolAddress(&p, g_S);    float* Sb   = (float*)p;
    cudaGetSymbolAddress(&p, g_Sh);   bf16* Sh   = (bf16*)p;
    cudaGetSymbolAddress(&p, g_Sl);   bf16* Sl   = (bf16*)p;
    cudaGetSymbolAddress(&p, g_erh);  bf16* erh  = (bf16*)p;
    cudaGetSymbolAddress(&p, g_erl);  bf16* erl  = (bf16*)p;
    cudaGetSymbolAddress(&p, g_er2h); bf16* er2h = (bf16*)p;
    cudaGetSymbolAddress(&p, g_er2l); bf16* er2l = (bf16*)p;
    cudaGetSymbolAddress(&p, g_KQh);  bf16* KQh  = (bf16*)p;
    cudaGetSymbolAddress(&p, g_KQl);  bf16* KQl  = (bf16*)p;
    cudaGetSymbolAddress(&p, g_Vth);  bf16* Vth  = (bf16*)p;
    cudaGetSymbolAddress(&p, g_Vtl);  bf16* Vtl  = (bf16*)p;
    cudaGetSymbolAddress(&p, g_r4h);  bf16* r4h  = (bf16*)p;
    cudaGetSymbolAddress(&p, g_r4l);  bf16* r4l  = (bf16*)p;
    cudaGetSymbolAddress(&p, g_e1h);  bf16* e1h  = (bf16*)p;
    cudaGetSymbolAddress(&p, g_e1l);  bf16* e1l  = (bf16*)p;
    cudaGetSymbolAddress(&p, g_e2h);  bf16* e2h  = (bf16*)p;
    cudaGetSymbolAddress(&p, g_e2l);  bf16* e2l  = (bf16*)p;
    cudaGetSymbolAddress(&p, g_e3h);  bf16* e3h  = (bf16*)p;
    cudaGetSymbolAddress(&p, g_e3l);  bf16* e3l  = (bf16*)p;
    cudaGetSymbolAddress(&p, g_k0h);  bf16* k0h  = (bf16*)p;
    cudaGetSymbolAddress(&p, g_k0l);  bf16* k0l  = (bf16*)p;
    cudaGetSymbolAddress(&p, g_Wth);  bf16* Wth  = (bf16*)p;
    cudaGetSymbolAddress(&p, g_Wtl);  bf16* Wtl  = (bf16*)p;

    const long WSET = 1310720;
    auto WH = [&](int grp, int i, long off){ return Wth + (long)(grp * 2 + i) * WSET + off; };
    auto WL = [&](int grp, int i, long off){ return Wtl + (long)(grp * 2 + i) * WSET + off; };

    // L1: batched square-weight transpose+split (12)
    {
        TS12 p12;
        int n = 0;
        for (int grp = 0; grp < 2; grp++) {
            const float* Wk = grp ? ca_Wk : sc_Wk;
            const float* Wq = grp ? ca_Wq : sc_Wq;
            const float* Wv = grp ? ca_Wv : sc_Wv;
            for (int i = 0; i < 2; i++) {
                p12.e[n++] = { Wk + (size_t)i * 262144, WH(grp, i, 0),      WL(grp, i, 0) };
                p12.e[n++] = { Wq + (size_t)i * 262144, WH(grp, i, 262144), WL(grp, i, 262144) };
                p12.e[n++] = { Wv + (size_t)i * 262144, WH(grp, i, 524288), WL(grp, i, 524288) };
            }
        }
        tsplit12_k<<<dim3(16, 16, 12), dim3(32, 8)>>>(p12);
    }
    // L2: batched Wf transpose+split (4)
    {
        TS4 p4;
        p4.e[0] = { sc_Wf,          WH(0, 0, 786432), WL(0, 0, 786432) };
        p4.e[1] = { sc_Wf + 524288, WH(0, 1, 786432), WL(0, 1, 786432) };
        p4.e[2] = { ca_Wf,          WH(1, 0, 786432), WL(1, 0, 786432) };
        p4.e[3] = { ca_Wf + 524288, WH(1, 1, 786432), WL(1, 1, 786432) };
        tsplit4_k<<<dim3(16, 32, 4), dim3(32, 8)>>>(p4);
    }

    // L3-5: input projections (e -> er planes; e1/e2 planes only)
    proj_in_k<<<TE / 256, 256>>>(cx, cy, in_W, in_b, e,       erh, erl, 1024, 0);
    proj_in_k<<<TE / 256, 256>>>(cx, cy, in_W, in_b, nullptr, e1h, e1l, 512,  1);
    proj_in_k<<<TE / 256, 256>>>(cx, cy, in_W, in_b, nullptr, e2h, e2l, 512,  2);

    const long DQ = (long)TOK * 1024;    // x2-half offset in KQ buffer
    const long TS_ = 8LL * 1024 * 1024;  // per-term S stride (fp32/plane elements)

    auto sc_layer = [&](const bf16* x2h, const bf16* x2l, bool self, int i) {
        const bf16 *WKQh = WH(0, i, 0),      *WKQl = WL(0, i, 0);
        const bf16 *WvTh = WH(0, i, 524288), *WvTl = WL(0, i, 524288);
        const bf16 *WfTh = WH(0, i, 786432), *WfTl = WL(0, i, 786432);
        const float* bfp = sc_bf + (size_t)i * CH;
        const float* lg  = sc_g  + (size_t)i * CH;
        const float* lb  = sc_b  + (size_t)i * CH;
        // [K|Q] = e @ [Wk|Wq]
        G<2>(erh, erl, 1024, 0, 0, WKQh, WKQl, 512, 0, 0,
             nullptr, KQh, KQl, 1024, 0, 0, TOK, 1024, 512, 1, 1, 1.f, nullptr);
        // Vt = Wv^T @ e^T  [CH, TOK]
        G<2>(WvTh, WvTl, 512, 0, 0, erh, erl, 1024, 0, 0,
             nullptr, Vth, Vtl, TOK, 0, 0, CH, TOK, 512, 1, 1, 1.f, nullptr);
        if (!self) {
            G<2>(x2h, x2l, 512, 0, 0, WKQh, WKQl, 512, 0, 0,
                 nullptr, KQh + DQ, KQl + DQ, 1024, 0, 0, TOK, 1024, 512, 1, 1, 1.f, nullptr);
            G<2>(WvTh, WvTl, 512, 0, 0, x2h, x2l, 512, 0, 0,
                 nullptr, Vth + TE, Vtl + TE, TOK, 0, 0, CH, TOK, 512, 1, 1, 1.f, nullptr);
        }
        int nT = self ? 1 : 4, Z = nT * 8;
        // QK batched over terms: A=Q side {x,x2,x2,x}, B=K side {x,x2? no: {x,x2,x,x2}}
        Tabs tq; memset(&tq, 0, sizeof(tq)); tq.nPerT = 8;
        long qa[4] = {0, DQ, DQ, 0}, kb[4] = {0, DQ, 0, DQ};
        for (int t = 0; t < 4; t++) { tq.a[t] = qa[t]; tq.b[t] = kb[t]; tq.c[t] = t * TS_; }
        G<1>(KQh + 512, KQl + 512, 1024, (long)CN * 1024, 256,
             KQh, KQl, 1024, (long)CN * 1024, 256,
             Sb, nullptr, nullptr, CN, 2L * CN * CN, (long)CN * CN,
             CN, CN, 256, Z, 2, 0.0625f, nullptr, &tq);
        softmax_k<<<Z * CN, 256>>>(Sb, Sh, Sl, self ? 4.f : 1.f);
        // SV batched: V side {V,V2,V,V2}
        Tabs tv; memset(&tv, 0, sizeof(tv)); tv.nPerT = 8;
        for (int t = 0; t < 4; t++) {
            tv.a[t] = t * TS_; tv.b[t] = (t & 1) ? (long)TE : 0;
            tv.c[t] = self ? 0 : (long)t * TE;
        }
        if (self)
            G<2>(Sh, Sl, CN, 2L * CN * CN, (long)CN * CN, Vth, Vtl, TOK, CN, 256L * TOK,
                 nullptr, erh + 512, erl + 512, 1024, (long)CN * 1024, 256,
                 CN, 256, CN, Z, 2, 1.f, nullptr, &tv);
        else {
            G<2>(Sh, Sl, CN, 2L * CN * CN, (long)CN * CN, Vth, Vtl, TOK, CN, 256L * TOK,
                 nullptr, r4h, r4l, CH, (long)CN * CH, 256,
                 CN, 256, CN, Z, 2, 1.f, nullptr, &tv);
            rsum_k<<<TE / 512, 256>>>(r4h, r4l, erh, erl);
        }
        // t = [e|r] @ WfT  (K=1024, one gemm)
        G<1>(erh, erl, 1024, 0, 0, WfTh, WfTl, 1024, 0, 0,
             tb, nullptr, nullptr, CH, 0, 0, TOK, CH, 1024, 1, 1, 1.f, bfp);
        add_ln_k<<<TOK, 256>>>(tb, e, lg, lb, e, erh, erl, 1024);
    };

    // L6.. : self layers first (launch #6 = the KQ GEMM -> ncu profiles tgemm)
    sc_layer(nullptr, nullptr, true, 0);
    sc_layer(nullptr, nullptr, true, 1);
    proj_in_k<<<TE / 256, 256>>>(cx, cy, in_W, in_b, nullptr, e3h, e3l, 512, 3);
    sc_layer(e1h, e1l, false, 0); sc_layer(e1h, e1l, false, 1);
    sc_layer(e2h, e2l, false, 0); sc_layer(e2h, e2l, false, 1);
    sc_layer(e3h, e3l, false, 0); sc_layer(e3h, e3l, false, 1);

    // cross-attn seeds
    proj1_k<<<TE / 256, 256>>>(txp, tx_W, tx_b, qb, er2h, er2l, 1024);
    proj1_k<<<TE / 256, 256>>>(cx, cx_W, cx_b, nullptr, k0h, k0l, 512);

    for (int i = 0; i < 2; i++) {
        const bf16 *cWkh = WH(1, i, 0),      *cWkl = WL(1, i, 0);
        const bf16 *cWqh = WH(1, i, 262144), *cWql = WL(1, i, 262144);
        const bf16 *cWvh = WH(1, i, 524288), *cWvl = WL(1, i, 524288);
        const bf16 *cWfh = WH(1, i, 786432), *cWfl = WL(1, i, 786432);
        const float* bfp = ca_bf + (size_t)i * CH;
        const float* lg  = ca_g  + (size_t)i * CH;
        const float* lb  = ca_b  + (size_t)i * CH;
        G<2>(k0h, k0l, 512, 0, 0, cWkh, cWkl, 512, 0, 0,
             nullptr, KQh, KQl, 1024, 0, 0, TOK, 512, 512, 1, 1, 1.f, nullptr);
        G<2>(er2h, er2l, 1024, 0, 0, cWqh, cWql, 512, 0, 0,
             nullptr, KQh + 512, KQl + 512, 1024, 0, 0, TOK, 512, 512, 1, 1, 1.f, nullptr);
        G<2>(cWvh, cWvl, 512, 0, 0, erh, erl, 1024, 0, 0,
             nullptr, Vth, Vtl, TOK, 0, 0, CH, TOK, 512, 1, 1, 1.f, nullptr);
        G<1>(KQh + 512, KQl + 512, 1024, (long)CM * 1024, 128,
             KQh, KQl, 1024, (long)CN * 1024, 128,
             Sb, nullptr, nullptr, CN, 4L * CM * CN, (long)CM * CN,
             CM, CN, 128, 16, 4, 0.0883883476483184f, nullptr);
        softmax_k<<<16 * CM, 256>>>(Sb, Sh, Sl, 1.f);
        G<2>(Sh, Sl, CN, 4L * CM * CN, (long)CM * CN, Vth, Vtl, TOK, CN, 128L * TOK,
             nullptr, er2h + 512, er2l + 512, 1024, (long)CM * 1024, 128,
             CM, 128, CN, 16, 4, 1.f, nullptr);
        G<1>(er2h, er2l, 1024, 0, 0, cWfh, cWfl, 1024, 0, 0,
             tb, nullptr, nullptr, CH, 0, 0, TOK, CH, 1024, 1, 1, 1.f, bfp);
        if (i == 1)
            add_ln_k<<<TOK, 256>>>(tb, qb, lg, lb, (float*)d_out, nullptr, nullptr, 0);
        else
            add_ln_k<<<TOK, 256>>>(tb, qb, lg, lb, qb, er2h, er2l, 1024);
    }
}